// round 1
// baseline (speedup 1.0000x reference)
#include <cuda_runtime.h>
#include <math.h>

#define CDIM 1024
#define NSEQ 2048
#define NBATCH 4
#define NHEAD 16
#define HDIM 64
#define RS 3072                 // qkv row stride
#define QK_SCALE 0.125f         // 1/sqrt(64)

// scratch for qkv projection: [B*N, 3*DIM] = 8192 x 3072 floats = 96 MB
__device__ float g_qkv[25165824];

// ============================================================================
// Kernel 1: qkv = X @ W^T + bias   (Q columns pre-scaled by QK_SCALE)
// X: [8192, 1024] row-major, W: [3072, 1024] row-major (K contiguous for both)
// Block tile 128x128, K-tile 16, 256 threads, 8x8 per thread (split 4+4).
// ============================================================================
__global__ __launch_bounds__(256, 2) void qkv_gemm(
    const float* __restrict__ X, const float* __restrict__ W,
    const float* __restrict__ bias)
{
    __shared__ float As[16][129];   // [k][m] transposed
    __shared__ float Bs[16][129];   // [k][n] transposed

    const int tid = threadIdx.x;
    const int tx  = tid & 15;
    const int ty  = tid >> 4;
    const int bm  = blockIdx.y * 128;
    const int bn  = blockIdx.x * 128;
    const int lr  = tid >> 2;            // 0..63 (load row)
    const int lc  = (tid & 3) << 2;      // 0,4,8,12 (load k-group)

    const float* Xp = X + (size_t)(bm + lr) * CDIM + lc;
    const float* Wp = W + (size_t)(bn + lr) * CDIM + lc;

    float acc[8][8];
    #pragma unroll
    for (int i = 0; i < 8; i++)
        #pragma unroll
        for (int j = 0; j < 8; j++) acc[i][j] = 0.0f;

    for (int k0 = 0; k0 < CDIM; k0 += 16) {
        float4 a0 = *(const float4*)(Xp + k0);
        float4 a1 = *(const float4*)(Xp + k0 + (size_t)64 * CDIM);
        float4 b0 = *(const float4*)(Wp + k0);
        float4 b1 = *(const float4*)(Wp + k0 + (size_t)64 * CDIM);
        __syncthreads();
        As[lc+0][lr]    = a0.x; As[lc+1][lr]    = a0.y;
        As[lc+2][lr]    = a0.z; As[lc+3][lr]    = a0.w;
        As[lc+0][lr+64] = a1.x; As[lc+1][lr+64] = a1.y;
        As[lc+2][lr+64] = a1.z; As[lc+3][lr+64] = a1.w;
        Bs[lc+0][lr]    = b0.x; Bs[lc+1][lr]    = b0.y;
        Bs[lc+2][lr]    = b0.z; Bs[lc+3][lr]    = b0.w;
        Bs[lc+0][lr+64] = b1.x; Bs[lc+1][lr+64] = b1.y;
        Bs[lc+2][lr+64] = b1.z; Bs[lc+3][lr+64] = b1.w;
        __syncthreads();

        #pragma unroll
        for (int k = 0; k < 16; k++) {
            float a[8], b[8];
            #pragma unroll
            for (int i = 0; i < 4; i++) {
                a[i]   = As[k][ty*4 + i];
                a[i+4] = As[k][64 + ty*4 + i];
            }
            #pragma unroll
            for (int j = 0; j < 4; j++) {
                b[j]   = Bs[k][tx*4 + j];
                b[j+4] = Bs[k][64 + tx*4 + j];
            }
            #pragma unroll
            for (int i = 0; i < 8; i++)
                #pragma unroll
                for (int j = 0; j < 8; j++)
                    acc[i][j] = fmaf(a[i], b[j], acc[i][j]);
        }
    }

    // epilogue: bias add, scale Q columns, store to scratch
    const float colscale = (bn < CDIM) ? QK_SCALE : 1.0f;
    float bv[8];
    #pragma unroll
    for (int j = 0; j < 4; j++) {
        bv[j]   = bias[bn + tx*4 + j];
        bv[j+4] = bias[bn + 64 + tx*4 + j];
    }
    #pragma unroll
    for (int i = 0; i < 8; i++) {
        const int m = bm + ((i < 4) ? (ty*4 + i) : (64 + ty*4 + (i-4)));
        float* orow = g_qkv + (size_t)m * RS + bn;
        float4 v0, v1;
        v0.x = (acc[i][0] + bv[0]) * colscale;
        v0.y = (acc[i][1] + bv[1]) * colscale;
        v0.z = (acc[i][2] + bv[2]) * colscale;
        v0.w = (acc[i][3] + bv[3]) * colscale;
        v1.x = (acc[i][4] + bv[4]) * colscale;
        v1.y = (acc[i][5] + bv[5]) * colscale;
        v1.z = (acc[i][6] + bv[6]) * colscale;
        v1.w = (acc[i][7] + bv[7]) * colscale;
        *(float4*)(orow + tx*4)      = v0;
        *(float4*)(orow + 64 + tx*4) = v1;
    }
}

// ============================================================================
// Kernel 2: flash attention, fp32. Block = (b, h, 64 q-rows).
// Q,K staged transposed [hd][row] (pad 65); V natural [key][hd] (pad 68);
// P staged [key][row] (pad 65). 256 threads as 16x16, 4x4 micro-tiles.
// ============================================================================
#define PADA 65
#define PADV 68
#define ATTN_SMEM ((3*64*PADA + 64*PADV) * 4)   // 67328 bytes

__global__ __launch_bounds__(256, 2) void attn_kernel(float* __restrict__ out)
{
    extern __shared__ float sm[];
    float* Qst = sm;                    // [hd][row]
    float* Kst = Qst + 64 * PADA;       // [hd][key]
    float* Ps  = Kst + 64 * PADA;       // [key][row]
    float* Vs  = Ps  + 64 * PADA;       // [key][hd]

    const int bh = blockIdx.y;
    const int b  = bh >> 4;
    const int h  = bh & 15;
    const int q0 = blockIdx.x << 6;
    const int tid = threadIdx.x;
    const int tx  = tid & 15;
    const int ty  = tid >> 4;

    const float* Qg = g_qkv + (size_t)(b * NSEQ) * RS + h * HDIM;
    const float* Kg = Qg + CDIM;
    const float* Vg = Qg + 2 * CDIM;

    const int lr = tid >> 2;            // 0..63
    const int lc = (tid & 3) << 2;      // 0,4,8,12

    // load Q tile transposed (already scaled by QK_SCALE in gemm)
    #pragma unroll
    for (int p = 0; p < 4; p++) {
        const int d0 = lc + p * 16;
        float4 v = *(const float4*)(Qg + (size_t)(q0 + lr) * RS + d0);
        Qst[(d0+0)*PADA + lr] = v.x;
        Qst[(d0+1)*PADA + lr] = v.y;
        Qst[(d0+2)*PADA + lr] = v.z;
        Qst[(d0+3)*PADA + lr] = v.w;
    }

    float m[4], l[4], o[4][4];
    #pragma unroll
    for (int i = 0; i < 4; i++) {
        m[i] = -1e30f; l[i] = 0.0f;
        #pragma unroll
        for (int j = 0; j < 4; j++) o[i][j] = 0.0f;
    }

    for (int kt = 0; kt < NSEQ / 64; kt++) {
        const int key0 = kt << 6;
        __syncthreads();   // prior iteration's Ps/Vs/Kst reads done
        #pragma unroll
        for (int p = 0; p < 4; p++) {
            const int d0 = lc + p * 16;
            float4 kv = *(const float4*)(Kg + (size_t)(key0 + lr) * RS + d0);
            Kst[(d0+0)*PADA + lr] = kv.x;
            Kst[(d0+1)*PADA + lr] = kv.y;
            Kst[(d0+2)*PADA + lr] = kv.z;
            Kst[(d0+3)*PADA + lr] = kv.w;
            float4 vv = *(const float4*)(Vg + (size_t)(key0 + lr) * RS + d0);
            *(float4*)(Vs + lr * PADV + d0) = vv;
        }
        __syncthreads();

        // S = Q @ K^T (4x4 per thread)
        float s[4][4];
        #pragma unroll
        for (int i = 0; i < 4; i++)
            #pragma unroll
            for (int j = 0; j < 4; j++) s[i][j] = 0.0f;

        #pragma unroll 8
        for (int d = 0; d < HDIM; d++) {
            float qf[4], kf[4];
            #pragma unroll
            for (int i = 0; i < 4; i++) qf[i] = Qst[d*PADA + ty*4 + i];
            #pragma unroll
            for (int j = 0; j < 4; j++) kf[j] = Kst[d*PADA + tx*4 + j];
            #pragma unroll
            for (int i = 0; i < 4; i++)
                #pragma unroll
                for (int j = 0; j < 4; j++)
                    s[i][j] = fmaf(qf[i], kf[j], s[i][j]);
        }

        // online softmax (row groups span 16 lanes within a warp)
        #pragma unroll
        for (int i = 0; i < 4; i++) {
            float rmax = fmaxf(fmaxf(s[i][0], s[i][1]), fmaxf(s[i][2], s[i][3]));
            #pragma unroll
            for (int off = 8; off >= 1; off >>= 1)
                rmax = fmaxf(rmax, __shfl_xor_sync(0xffffffffu, rmax, off));
            const float newm = fmaxf(m[i], rmax);
            const float corr = __expf(m[i] - newm);
            float rsum = 0.0f;
            #pragma unroll
            for (int j = 0; j < 4; j++) {
                s[i][j] = __expf(s[i][j] - newm);
                rsum += s[i][j];
            }
            #pragma unroll
            for (int off = 8; off >= 1; off >>= 1)
                rsum += __shfl_xor_sync(0xffffffffu, rsum, off);
            l[i] = l[i] * corr + rsum;
            #pragma unroll
            for (int j = 0; j < 4; j++) o[i][j] *= corr;
            m[i] = newm;
        }

        // stage P transposed: Ps[key][row]
        #pragma unroll
        for (int j = 0; j < 4; j++)
            #pragma unroll
            for (int i = 0; i < 4; i++)
                Ps[(tx*4 + j)*PADA + ty*4 + i] = s[i][j];
        __syncthreads();

        // O += P @ V
        #pragma unroll 8
        for (int kk = 0; kk < 64; kk++) {
            float pf[4];
            #pragma unroll
            for (int i = 0; i < 4; i++) pf[i] = Ps[kk*PADA + ty*4 + i];
            float4 vf = *(const float4*)(Vs + kk*PADV + tx*4);
            #pragma unroll
            for (int i = 0; i < 4; i++) {
                o[i][0] = fmaf(pf[i], vf.x, o[i][0]);
                o[i][1] = fmaf(pf[i], vf.y, o[i][1]);
                o[i][2] = fmaf(pf[i], vf.z, o[i][2]);
                o[i][3] = fmaf(pf[i], vf.w, o[i][3]);
            }
        }
    }

    // epilogue: normalize, write out[b, n, h*64 + hd]
    #pragma unroll
    for (int i = 0; i < 4; i++) {
        const float inv = 1.0f / l[i];
        float4 v;
        v.x = o[i][0] * inv; v.y = o[i][1] * inv;
        v.z = o[i][2] * inv; v.w = o[i][3] * inv;
        *(float4*)(out + (size_t)(b * NSEQ + q0 + ty*4 + i) * CDIM
                       + h * HDIM + tx*4) = v;
    }
}

extern "C" void kernel_launch(void* const* d_in, const int* in_sizes, int n_in,
                              void* d_out, int out_size)
{
    const float* x    = (const float*)d_in[0];
    const float* w    = (const float*)d_in[1];
    const float* bias = (const float*)d_in[2];
    float* out = (float*)d_out;

    cudaFuncSetAttribute(attn_kernel,
                         cudaFuncAttributeMaxDynamicSharedMemorySize, ATTN_SMEM);

    // QKV projection: grid (3072/128, 8192/128)
    qkv_gemm<<<dim3(24, 64), 256>>>(x, w, bias);

    // attention: grid (2048/64 q-tiles, B*H)
    attn_kernel<<<dim3(32, 64), 256, ATTN_SMEM>>>(out);
}

// round 3
// speedup vs baseline: 1.0710x; 1.0710x over previous
#include <cuda_runtime.h>
#include <math.h>
#include <stdint.h>

#define CDIM 1024
#define NSEQ 2048
#define NHEAD 16
#define HDIM 64
#define RS 3072                 // qkv row stride
#define QK_SCALE 0.125f

// scratch for qkv projection: [B*N, 3*DIM] = 8192 x 3072 floats = 96 MB
__device__ float g_qkv[25165824];

__device__ __forceinline__ uint32_t smem_u32(const void* p) {
    return (uint32_t)__cvta_generic_to_shared(p);
}
__device__ __forceinline__ uint32_t f2tf32(float f) {
    uint32_t r;
    asm("cvt.rna.tf32.f32 %0, %1;" : "=r"(r) : "f"(f));
    return r;
}

#define MMA_TF32(d, a, b) \
    asm volatile( \
        "mma.sync.aligned.m16n8k8.row.col.f32.tf32.tf32.f32 " \
        "{%0,%1,%2,%3}, {%4,%5,%6,%7}, {%8,%9}, {%0,%1,%2,%3};" \
        : "+f"((d)[0]), "+f"((d)[1]), "+f"((d)[2]), "+f"((d)[3]) \
        : "r"((a)[0]), "r"((a)[1]), "r"((a)[2]), "r"((a)[3]), \
          "r"((b)[0]), "r"((b)[1]))

// ============================================================================
// Kernel 1: mma.sync tf32x3 GEMM.  qkv = X @ W^T + bias (Q cols pre-scaled)
// Tile 128x128, Ktile 32, 256 thr (2x4 warps, 64x32/warp), 3-stage cp.async.
// smem: fp32 tiles [128][36] (pad 36 -> conflict-free frag loads, 16B-aligned
// rows for cp.async). hi/lo tf32 split in registers (3xTF32, drop lo*lo).
// ============================================================================
#define SROW 36                       // floats per smem row (144B)
#define STAGE_F (2 * 128 * SROW)      // 9216 floats per stage (A+B)
#define GEMM_DSMEM (3 * STAGE_F * 4)  // 110592 bytes

__global__ __launch_bounds__(256, 1) void qkv_gemm_tc(
    const float* __restrict__ X, const float* __restrict__ W,
    const float* __restrict__ bias)
{
    extern __shared__ float smg[];
    const int t    = threadIdx.x;
    const int wid  = t >> 5;
    const int lane = t & 31;
    const int gid  = lane >> 2;       // 0..7
    const int tig  = lane & 3;        // 0..3
    const int wm   = wid >> 2;        // 0..1 (m: 64 rows)
    const int wn   = wid & 3;         // 0..3 (n: 32 cols)
    const int bm   = blockIdx.y * 128;
    const int bn   = blockIdx.x * 128;

    float acc[4][4][4];
    #pragma unroll
    for (int mi = 0; mi < 4; mi++)
        #pragma unroll
        for (int ni = 0; ni < 4; ni++)
            #pragma unroll
            for (int r = 0; r < 4; r++) acc[mi][ni][r] = 0.0f;

    const int lrow = t >> 3;          // 0..31  (x4 for loads)
    const int lc4  = t & 7;           // float4 index within 32-float row

    auto load_stage = [&](int s) {
        float* A  = smg + (s % 3) * STAGE_F;
        const uint32_t ab = smem_u32(A);
        const uint32_t bb = ab + 128 * SROW * 4;
        #pragma unroll
        for (int i = 0; i < 4; i++) {
            const int row = i * 32 + lrow;
            const uint32_t so = (uint32_t)(row * (SROW * 4) + lc4 * 16);
            const float* sa = X + (size_t)(bm + row) * CDIM + s * 32 + lc4 * 4;
            const float* sw = W + (size_t)(bn + row) * CDIM + s * 32 + lc4 * 4;
            asm volatile("cp.async.cg.shared.global [%0], [%1], 16;"
                         :: "r"(ab + so), "l"(sa) : "memory");
            asm volatile("cp.async.cg.shared.global [%0], [%1], 16;"
                         :: "r"(bb + so), "l"(sw) : "memory");
        }
        asm volatile("cp.async.commit_group;" ::: "memory");
    };

    load_stage(0);
    load_stage(1);

    for (int kt = 0; kt < CDIM / 32; kt++) {
        asm volatile("cp.async.wait_group 1;" ::: "memory");
        __syncthreads();

        if (kt + 2 < CDIM / 32) load_stage(kt + 2);
        else asm volatile("cp.async.commit_group;" ::: "memory");  // keep count

        const float* A  = smg + (kt % 3) * STAGE_F;
        const float* Bs = A + 128 * SROW;

        #pragma unroll
        for (int ks = 0; ks < 4; ks++) {
            const int k0 = ks * 8 + tig;
            uint32_t ahi[4][4], alo[4][4], bhi[4][2], blo[4][2];
            #pragma unroll
            for (int mi = 0; mi < 4; mi++) {
                const int r0 = (wm * 64 + mi * 16 + gid) * SROW;
                float a0 = A[r0 + k0];
                float a1 = A[r0 + 8 * SROW + k0];
                float a2 = A[r0 + k0 + 4];
                float a3 = A[r0 + 8 * SROW + k0 + 4];
                ahi[mi][0] = f2tf32(a0); alo[mi][0] = f2tf32(a0 - __uint_as_float(ahi[mi][0]));
                ahi[mi][1] = f2tf32(a1); alo[mi][1] = f2tf32(a1 - __uint_as_float(ahi[mi][1]));
                ahi[mi][2] = f2tf32(a2); alo[mi][2] = f2tf32(a2 - __uint_as_float(ahi[mi][2]));
                ahi[mi][3] = f2tf32(a3); alo[mi][3] = f2tf32(a3 - __uint_as_float(ahi[mi][3]));
            }
            #pragma unroll
            for (int ni = 0; ni < 4; ni++) {
                const int n0 = (wn * 32 + ni * 8 + gid) * SROW;
                float b0 = Bs[n0 + k0];
                float b1 = Bs[n0 + k0 + 4];
                bhi[ni][0] = f2tf32(b0); blo[ni][0] = f2tf32(b0 - __uint_as_float(bhi[ni][0]));
                bhi[ni][1] = f2tf32(b1); blo[ni][1] = f2tf32(b1 - __uint_as_float(bhi[ni][1]));
            }
            #pragma unroll
            for (int mi = 0; mi < 4; mi++)
                #pragma unroll
                for (int ni = 0; ni < 4; ni++) {
                    MMA_TF32(acc[mi][ni], ahi[mi], bhi[ni]);
                    MMA_TF32(acc[mi][ni], ahi[mi], blo[ni]);
                    MMA_TF32(acc[mi][ni], alo[mi], bhi[ni]);
                }
        }
        __syncthreads();
    }

    // epilogue: bias + Q scale, write g_qkv
    const float cs = (bn < CDIM) ? QK_SCALE : 1.0f;
    #pragma unroll
    for (int mi = 0; mi < 4; mi++) {
        const int r0 = bm + wm * 64 + mi * 16 + gid;
        #pragma unroll
        for (int ni = 0; ni < 4; ni++) {
            const int c = bn + wn * 32 + ni * 8 + tig * 2;
            const float b0 = bias[c], b1 = bias[c + 1];
            float2 v0, v1;
            v0.x = (acc[mi][ni][0] + b0) * cs;
            v0.y = (acc[mi][ni][1] + b1) * cs;
            v1.x = (acc[mi][ni][2] + b0) * cs;
            v1.y = (acc[mi][ni][3] + b1) * cs;
            *(float2*)(g_qkv + (size_t)r0 * RS + c)       = v0;
            *(float2*)(g_qkv + (size_t)(r0 + 8) * RS + c) = v1;
        }
    }
}

// ============================================================================
// Kernel 2: flash attention, fp32 (unchanged, proven).
// ============================================================================
#define PADA 65
#define PADV 68
#define ATTN_SMEM ((3 * 64 * PADA + 64 * PADV) * 4)

__global__ __launch_bounds__(256, 2) void attn_kernel(float* __restrict__ out)
{
    extern __shared__ float sm[];
    float* Qst = sm;
    float* Kst = Qst + 64 * PADA;
    float* Ps  = Kst + 64 * PADA;
    float* Vs  = Ps  + 64 * PADA;

    const int bh = blockIdx.y;
    const int b  = bh >> 4;
    const int h  = bh & 15;
    const int q0 = blockIdx.x << 6;
    const int tid = threadIdx.x;
    const int tx  = tid & 15;
    const int ty  = tid >> 4;

    const float* Qg = g_qkv + (size_t)(b * NSEQ) * RS + h * HDIM;
    const float* Kg = Qg + CDIM;
    const float* Vg = Qg + 2 * CDIM;

    const int lr = tid >> 2;
    const int lc = (tid & 3) << 2;

    #pragma unroll
    for (int p = 0; p < 4; p++) {
        const int d0 = lc + p * 16;
        float4 v = *(const float4*)(Qg + (size_t)(q0 + lr) * RS + d0);
        Qst[(d0+0)*PADA + lr] = v.x;
        Qst[(d0+1)*PADA + lr] = v.y;
        Qst[(d0+2)*PADA + lr] = v.z;
        Qst[(d0+3)*PADA + lr] = v.w;
    }

    float m[4], l[4], o[4][4];
    #pragma unroll
    for (int i = 0; i < 4; i++) {
        m[i] = -1e30f; l[i] = 0.0f;
        #pragma unroll
        for (int j = 0; j < 4; j++) o[i][j] = 0.0f;
    }

    for (int kt = 0; kt < NSEQ / 64; kt++) {
        const int key0 = kt << 6;
        __syncthreads();
        #pragma unroll
        for (int p = 0; p < 4; p++) {
            const int d0 = lc + p * 16;
            float4 kv = *(const float4*)(Kg + (size_t)(key0 + lr) * RS + d0);
            Kst[(d0+0)*PADA + lr] = kv.x;
            Kst[(d0+1)*PADA + lr] = kv.y;
            Kst[(d0+2)*PADA + lr] = kv.z;
            Kst[(d0+3)*PADA + lr] = kv.w;
            float4 vv = *(const float4*)(Vg + (size_t)(key0 + lr) * RS + d0);
            *(float4*)(Vs + lr * PADV + d0) = vv;
        }
        __syncthreads();

        float s[4][4];
        #pragma unroll
        for (int i = 0; i < 4; i++)
            #pragma unroll
            for (int j = 0; j < 4; j++) s[i][j] = 0.0f;

        #pragma unroll 8
        for (int d = 0; d < HDIM; d++) {
            float qf[4], kf[4];
            #pragma unroll
            for (int i = 0; i < 4; i++) qf[i] = Qst[d*PADA + ty*4 + i];
            #pragma unroll
            for (int j = 0; j < 4; j++) kf[j] = Kst[d*PADA + tx*4 + j];
            #pragma unroll
            for (int i = 0; i < 4; i++)
                #pragma unroll
                for (int j = 0; j < 4; j++)
                    s[i][j] = fmaf(qf[i], kf[j], s[i][j]);
        }

        #pragma unroll
        for (int i = 0; i < 4; i++) {
            float rmax = fmaxf(fmaxf(s[i][0], s[i][1]), fmaxf(s[i][2], s[i][3]));
            #pragma unroll
            for (int off = 8; off >= 1; off >>= 1)
                rmax = fmaxf(rmax, __shfl_xor_sync(0xffffffffu, rmax, off));
            const float newm = fmaxf(m[i], rmax);
            const float corr = __expf(m[i] - newm);
            float rsum = 0.0f;
            #pragma unroll
            for (int j = 0; j < 4; j++) {
                s[i][j] = __expf(s[i][j] - newm);
                rsum += s[i][j];
            }
            #pragma unroll
            for (int off = 8; off >= 1; off >>= 1)
                rsum += __shfl_xor_sync(0xffffffffu, rsum, off);
            l[i] = l[i] * corr + rsum;
            #pragma unroll
            for (int j = 0; j < 4; j++) o[i][j] *= corr;
            m[i] = newm;
        }

        #pragma unroll
        for (int j = 0; j < 4; j++)
            #pragma unroll
            for (int i = 0; i < 4; i++)
                Ps[(tx*4 + j)*PADA + ty*4 + i] = s[i][j];
        __syncthreads();

        #pragma unroll 8
        for (int kk = 0; kk < 64; kk++) {
            float pf[4];
            #pragma unroll
            for (int i = 0; i < 4; i++) pf[i] = Ps[kk*PADA + ty*4 + i];
            float4 vf = *(const float4*)(Vs + kk*PADV + tx*4);
            #pragma unroll
            for (int i = 0; i < 4; i++) {
                o[i][0] = fmaf(pf[i], vf.x, o[i][0]);
                o[i][1] = fmaf(pf[i], vf.y, o[i][1]);
                o[i][2] = fmaf(pf[i], vf.z, o[i][2]);
                o[i][3] = fmaf(pf[i], vf.w, o[i][3]);
            }
        }
    }

    #pragma unroll
    for (int i = 0; i < 4; i++) {
        const float inv = 1.0f / l[i];
        float4 v;
        v.x = o[i][0] * inv; v.y = o[i][1] * inv;
        v.z = o[i][2] * inv; v.w = o[i][3] * inv;
        *(float4*)(out + (size_t)(b * NSEQ + q0 + ty*4 + i) * CDIM
                       + h * HDIM + tx*4) = v;
    }
}

extern "C" void kernel_launch(void* const* d_in, const int* in_sizes, int n_in,
                              void* d_out, int out_size)
{
    const float* x    = (const float*)d_in[0];
    const float* w    = (const float*)d_in[1];
    const float* bias = (const float*)d_in[2];
    float* out = (float*)d_out;

    cudaFuncSetAttribute(qkv_gemm_tc,
                         cudaFuncAttributeMaxDynamicSharedMemorySize, GEMM_DSMEM);
    cudaFuncSetAttribute(attn_kernel,
                         cudaFuncAttributeMaxDynamicSharedMemorySize, ATTN_SMEM);

    qkv_gemm_tc<<<dim3(24, 64), 256, GEMM_DSMEM>>>(x, w, bias);
    attn_kernel<<<dim3(32, 64), 256, ATTN_SMEM>>>(out);
}

// round 4
// speedup vs baseline: 1.6625x; 1.5523x over previous
#include <cuda_runtime.h>
#include <math.h>
#include <stdint.h>

#define CDIM 1024
#define NSEQ 2048
#define NHEAD 16
#define HDIM 64
#define RS 3072
#define QK_SCALE 0.125f

__device__ float g_qkv[25165824];   // [8192][3072] qkv scratch

__device__ __forceinline__ uint32_t smem_u32(const void* p) {
    return (uint32_t)__cvta_generic_to_shared(p);
}
__device__ __forceinline__ uint32_t f2tf32(float f) {
    uint32_t r;
    asm("cvt.rna.tf32.f32 %0, %1;" : "=r"(r) : "f"(f));
    return r;
}

#define MMA_TF32(d, a, b0, b1) \
    asm volatile( \
        "mma.sync.aligned.m16n8k8.row.col.f32.tf32.tf32.f32 " \
        "{%0,%1,%2,%3}, {%4,%5,%6,%7}, {%8,%9}, {%0,%1,%2,%3};" \
        : "+f"((d)[0]), "+f"((d)[1]), "+f"((d)[2]), "+f"((d)[3]) \
        : "r"((a)[0]), "r"((a)[1]), "r"((a)[2]), "r"((a)[3]), \
          "r"(b0), "r"(b1))

// ============================================================================
// Kernel 1: mma.sync tf32x3 GEMM (unchanged from round 3, proven).
// ============================================================================
#define SROW 36
#define STAGE_F (2 * 128 * SROW)
#define GEMM_DSMEM (3 * STAGE_F * 4)

__global__ __launch_bounds__(256, 1) void qkv_gemm_tc(
    const float* __restrict__ X, const float* __restrict__ W,
    const float* __restrict__ bias)
{
    extern __shared__ float smg[];
    const int t    = threadIdx.x;
    const int wid  = t >> 5;
    const int lane = t & 31;
    const int gid  = lane >> 2;
    const int tig  = lane & 3;
    const int wm   = wid >> 2;
    const int wn   = wid & 3;
    const int bm   = blockIdx.y * 128;
    const int bn   = blockIdx.x * 128;

    float acc[4][4][4];
    #pragma unroll
    for (int mi = 0; mi < 4; mi++)
        #pragma unroll
        for (int ni = 0; ni < 4; ni++)
            #pragma unroll
            for (int r = 0; r < 4; r++) acc[mi][ni][r] = 0.0f;

    const int lrow = t >> 3;
    const int lc4  = t & 7;

    auto load_stage = [&](int s) {
        float* A  = smg + (s % 3) * STAGE_F;
        const uint32_t ab = smem_u32(A);
        const uint32_t bb = ab + 128 * SROW * 4;
        #pragma unroll
        for (int i = 0; i < 4; i++) {
            const int row = i * 32 + lrow;
            const uint32_t so = (uint32_t)(row * (SROW * 4) + lc4 * 16);
            const float* sa = X + (size_t)(bm + row) * CDIM + s * 32 + lc4 * 4;
            const float* sw = W + (size_t)(bn + row) * CDIM + s * 32 + lc4 * 4;
            asm volatile("cp.async.cg.shared.global [%0], [%1], 16;"
                         :: "r"(ab + so), "l"(sa) : "memory");
            asm volatile("cp.async.cg.shared.global [%0], [%1], 16;"
                         :: "r"(bb + so), "l"(sw) : "memory");
        }
        asm volatile("cp.async.commit_group;" ::: "memory");
    };

    load_stage(0);
    load_stage(1);

    for (int kt = 0; kt < CDIM / 32; kt++) {
        asm volatile("cp.async.wait_group 1;" ::: "memory");
        __syncthreads();

        if (kt + 2 < CDIM / 32) load_stage(kt + 2);
        else asm volatile("cp.async.commit_group;" ::: "memory");

        const float* A  = smg + (kt % 3) * STAGE_F;
        const float* Bs = A + 128 * SROW;

        #pragma unroll
        for (int ks = 0; ks < 4; ks++) {
            const int k0 = ks * 8 + tig;
            uint32_t ahi[4][4], alo[4][4], bhi[4][2], blo[4][2];
            #pragma unroll
            for (int mi = 0; mi < 4; mi++) {
                const int r0 = (wm * 64 + mi * 16 + gid) * SROW;
                float a0 = A[r0 + k0];
                float a1 = A[r0 + 8 * SROW + k0];
                float a2 = A[r0 + k0 + 4];
                float a3 = A[r0 + 8 * SROW + k0 + 4];
                ahi[mi][0] = f2tf32(a0); alo[mi][0] = f2tf32(a0 - __uint_as_float(ahi[mi][0]));
                ahi[mi][1] = f2tf32(a1); alo[mi][1] = f2tf32(a1 - __uint_as_float(ahi[mi][1]));
                ahi[mi][2] = f2tf32(a2); alo[mi][2] = f2tf32(a2 - __uint_as_float(ahi[mi][2]));
                ahi[mi][3] = f2tf32(a3); alo[mi][3] = f2tf32(a3 - __uint_as_float(ahi[mi][3]));
            }
            #pragma unroll
            for (int ni = 0; ni < 4; ni++) {
                const int n0 = (wn * 32 + ni * 8 + gid) * SROW;
                float b0 = Bs[n0 + k0];
                float b1 = Bs[n0 + k0 + 4];
                bhi[ni][0] = f2tf32(b0); blo[ni][0] = f2tf32(b0 - __uint_as_float(bhi[ni][0]));
                bhi[ni][1] = f2tf32(b1); blo[ni][1] = f2tf32(b1 - __uint_as_float(bhi[ni][1]));
            }
            #pragma unroll
            for (int mi = 0; mi < 4; mi++)
                #pragma unroll
                for (int ni = 0; ni < 4; ni++) {
                    MMA_TF32(acc[mi][ni], ahi[mi], bhi[ni][0], bhi[ni][1]);
                    MMA_TF32(acc[mi][ni], ahi[mi], blo[ni][0], blo[ni][1]);
                    MMA_TF32(acc[mi][ni], alo[mi], bhi[ni][0], bhi[ni][1]);
                }
        }
        __syncthreads();
    }

    const float cs = (bn < CDIM) ? QK_SCALE : 1.0f;
    #pragma unroll
    for (int mi = 0; mi < 4; mi++) {
        const int r0 = bm + wm * 64 + mi * 16 + gid;
        #pragma unroll
        for (int ni = 0; ni < 4; ni++) {
            const int c = bn + wn * 32 + ni * 8 + tig * 2;
            const float b0 = bias[c], b1 = bias[c + 1];
            float2 v0, v1;
            v0.x = (acc[mi][ni][0] + b0) * cs;
            v0.y = (acc[mi][ni][1] + b1) * cs;
            v1.x = (acc[mi][ni][2] + b0) * cs;
            v1.y = (acc[mi][ni][3] + b1) * cs;
            *(float2*)(g_qkv + (size_t)r0 * RS + c)       = v0;
            *(float2*)(g_qkv + (size_t)(r0 + 8) * RS + c) = v1;
        }
    }
}

// ============================================================================
// Kernel 2: tensor-core flash attention.
// Block: 128 q-rows x (b,h). 8 warps x (16 q-rows, all 64 keys of kv-tile).
// QK: 3xtf32 (Q hi/lo frags in regs). PV: phi*vhi + phi*vlo.
// smem u32 arrays: Khi/Klo [64][68], Vhi/Vlo [64][72], Phi [128][68]
// (pads make every frag LDS conflict-free). Q staged in Phi region.
// ============================================================================
#define KHI_OFF 0
#define KLO_OFF 4352
#define VHI_OFF 8704
#define VLO_OFF 13312
#define PHI_OFF 17920
#define ATTN_DSMEM ((26624) * 4)   // 106496 bytes

__global__ __launch_bounds__(256, 1) void attn_tc(float* __restrict__ out)
{
    extern __shared__ uint32_t sb[];
    uint32_t* Khi = sb + KHI_OFF;
    uint32_t* Klo = sb + KLO_OFF;
    uint32_t* Vhi = sb + VHI_OFF;
    uint32_t* Vlo = sb + VLO_OFF;
    uint32_t* Phi = sb + PHI_OFF;
    float*    Qs  = (float*)(sb + PHI_OFF);   // staging view [128][65]

    const int tid  = threadIdx.x;
    const int wid  = tid >> 5;
    const int lane = tid & 31;
    const int r    = lane >> 2;
    const int tig  = lane & 3;
    const int bh   = blockIdx.y;
    const int b    = bh >> 4;
    const int h    = bh & 15;
    const int q0   = blockIdx.x << 7;

    const float* Qg = g_qkv + (size_t)(b * NSEQ) * RS + h * HDIM;
    const float* Kg = Qg + CDIM;
    const float* Vg = Qg + 2 * CDIM;

    // ---- stage Q (f32) into Phi region ----
    #pragma unroll
    for (int i = 0; i < 8; i++) {
        const int idx = i * 256 + tid;            // 2048 float4s
        const int row = idx >> 4;
        const int c4  = (idx & 15) << 2;
        float4 v = *(const float4*)(Qg + (size_t)(q0 + row) * RS + c4);
        float* d = Qs + row * 65 + c4;
        d[0] = v.x; d[1] = v.y; d[2] = v.z; d[3] = v.w;
    }

    // ---- prefetch K/V tile 0 into registers ----
    float4 kreg[4], vreg[4];
    auto ldg_tile = [&](int t) {
        const int key0 = t << 6;
        #pragma unroll
        for (int j = 0; j < 4; j++) {
            const int idx = j * 256 + tid;        // 1024 float4s per tile
            const int key = idx >> 4;
            const int c4  = (idx & 15) << 2;
            kreg[j] = *(const float4*)(Kg + (size_t)(key0 + key) * RS + c4);
            vreg[j] = *(const float4*)(Vg + (size_t)(key0 + key) * RS + c4);
        }
    };
    ldg_tile(0);
    __syncthreads();

    // ---- Q frags (hi/lo) into registers, rows R0..R0+15 ----
    const int R0 = wid << 4;
    uint32_t qhi[8][4], qlo[8][4];
    #pragma unroll
    for (int kt = 0; kt < 8; kt++) {
        const int k0 = kt * 8 + tig;
        float a0 = Qs[(R0 + r) * 65 + k0];
        float a1 = Qs[(R0 + r + 8) * 65 + k0];
        float a2 = Qs[(R0 + r) * 65 + k0 + 4];
        float a3 = Qs[(R0 + r + 8) * 65 + k0 + 4];
        qhi[kt][0] = f2tf32(a0); qlo[kt][0] = f2tf32(a0 - __uint_as_float(qhi[kt][0]));
        qhi[kt][1] = f2tf32(a1); qlo[kt][1] = f2tf32(a1 - __uint_as_float(qhi[kt][1]));
        qhi[kt][2] = f2tf32(a2); qlo[kt][2] = f2tf32(a2 - __uint_as_float(qhi[kt][2]));
        qhi[kt][3] = f2tf32(a3); qlo[kt][3] = f2tf32(a3 - __uint_as_float(qhi[kt][3]));
    }

    float oacc[8][4];
    #pragma unroll
    for (int nt = 0; nt < 8; nt++)
        #pragma unroll
        for (int c = 0; c < 4; c++) oacc[nt][c] = 0.0f;
    float m0 = -1e30f, m1 = -1e30f, l0 = 0.0f, l1 = 0.0f;

    const int rl = R0 + r;
    const int rh = rl + 8;

    #pragma unroll 1
    for (int t = 0; t < NSEQ / 64; t++) {
        // ---- convert + store K/V hi/lo ----
        #pragma unroll
        for (int j = 0; j < 4; j++) {
            const int idx = j * 256 + tid;
            const int key = idx >> 4;
            const int c0  = (idx & 15) << 2;
            uint4 hi, lo;
            hi.x = f2tf32(kreg[j].x); lo.x = f2tf32(kreg[j].x - __uint_as_float(hi.x));
            hi.y = f2tf32(kreg[j].y); lo.y = f2tf32(kreg[j].y - __uint_as_float(hi.y));
            hi.z = f2tf32(kreg[j].z); lo.z = f2tf32(kreg[j].z - __uint_as_float(hi.z));
            hi.w = f2tf32(kreg[j].w); lo.w = f2tf32(kreg[j].w - __uint_as_float(hi.w));
            *(uint4*)(Khi + key * 68 + c0) = hi;
            *(uint4*)(Klo + key * 68 + c0) = lo;
            hi.x = f2tf32(vreg[j].x); lo.x = f2tf32(vreg[j].x - __uint_as_float(hi.x));
            hi.y = f2tf32(vreg[j].y); lo.y = f2tf32(vreg[j].y - __uint_as_float(hi.y));
            hi.z = f2tf32(vreg[j].z); lo.z = f2tf32(vreg[j].z - __uint_as_float(hi.z));
            hi.w = f2tf32(vreg[j].w); lo.w = f2tf32(vreg[j].w - __uint_as_float(hi.w));
            *(uint4*)(Vhi + key * 72 + c0) = hi;
            *(uint4*)(Vlo + key * 72 + c0) = lo;
        }
        __syncthreads();

        if (t + 1 < NSEQ / 64) ldg_tile(t + 1);   // hidden under compute

        // ---- S = Q @ K^T (3xtf32) ----
        float sacc[8][4];
        #pragma unroll
        for (int nt = 0; nt < 8; nt++)
            #pragma unroll
            for (int c = 0; c < 4; c++) sacc[nt][c] = 0.0f;

        #pragma unroll
        for (int kt = 0; kt < 8; kt++) {
            const int k0 = kt * 8 + tig;
            #pragma unroll
            for (int nt = 0; nt < 8; nt++) {
                const int n0 = (nt * 8 + r) * 68;
                uint32_t b0h = Khi[n0 + k0], b1h = Khi[n0 + k0 + 4];
                uint32_t b0l = Klo[n0 + k0], b1l = Klo[n0 + k0 + 4];
                MMA_TF32(sacc[nt], qhi[kt], b0h, b1h);
                MMA_TF32(sacc[nt], qhi[kt], b0l, b1l);
                MMA_TF32(sacc[nt], qlo[kt], b0h, b1h);
            }
        }

        // ---- online softmax (rows rl, rh; cols live in 4-lane quad) ----
        float mx0 = -1e30f, mx1 = -1e30f;
        #pragma unroll
        for (int nt = 0; nt < 8; nt++) {
            mx0 = fmaxf(mx0, fmaxf(sacc[nt][0], sacc[nt][1]));
            mx1 = fmaxf(mx1, fmaxf(sacc[nt][2], sacc[nt][3]));
        }
        mx0 = fmaxf(mx0, __shfl_xor_sync(0xffffffffu, mx0, 1));
        mx0 = fmaxf(mx0, __shfl_xor_sync(0xffffffffu, mx0, 2));
        mx1 = fmaxf(mx1, __shfl_xor_sync(0xffffffffu, mx1, 1));
        mx1 = fmaxf(mx1, __shfl_xor_sync(0xffffffffu, mx1, 2));
        const float nm0 = fmaxf(m0, mx0), nm1 = fmaxf(m1, mx1);
        const float cr0 = __expf(m0 - nm0), cr1 = __expf(m1 - nm1);
        float sum0 = 0.0f, sum1 = 0.0f;
        #pragma unroll
        for (int nt = 0; nt < 8; nt++) {
            sacc[nt][0] = __expf(sacc[nt][0] - nm0);
            sacc[nt][1] = __expf(sacc[nt][1] - nm0);
            sacc[nt][2] = __expf(sacc[nt][2] - nm1);
            sacc[nt][3] = __expf(sacc[nt][3] - nm1);
            sum0 += sacc[nt][0] + sacc[nt][1];
            sum1 += sacc[nt][2] + sacc[nt][3];
        }
        sum0 += __shfl_xor_sync(0xffffffffu, sum0, 1);
        sum0 += __shfl_xor_sync(0xffffffffu, sum0, 2);
        sum1 += __shfl_xor_sync(0xffffffffu, sum1, 1);
        sum1 += __shfl_xor_sync(0xffffffffu, sum1, 2);
        l0 = l0 * cr0 + sum0; m0 = nm0;
        l1 = l1 * cr1 + sum1; m1 = nm1;
        #pragma unroll
        for (int nt = 0; nt < 8; nt++) {
            oacc[nt][0] *= cr0; oacc[nt][1] *= cr0;
            oacc[nt][2] *= cr1; oacc[nt][3] *= cr1;
        }

        // ---- P -> tf32 -> smem ----
        #pragma unroll
        for (int nt = 0; nt < 8; nt++) {
            const int c = nt * 8 + tig * 2;
            uint64_t p0 = (uint64_t)f2tf32(sacc[nt][0])
                        | ((uint64_t)f2tf32(sacc[nt][1]) << 32);
            uint64_t p1 = (uint64_t)f2tf32(sacc[nt][2])
                        | ((uint64_t)f2tf32(sacc[nt][3]) << 32);
            *(uint64_t*)(Phi + rl * 68 + c) = p0;
            *(uint64_t*)(Phi + rh * 68 + c) = p1;
        }
        __syncthreads();

        // ---- O += P @ V (phi*vhi + phi*vlo) ----
        #pragma unroll
        for (int kt = 0; kt < 8; kt++) {
            const int k0 = kt * 8 + tig;
            uint32_t a[4];
            a[0] = Phi[rl * 68 + k0];
            a[1] = Phi[rh * 68 + k0];
            a[2] = Phi[rl * 68 + k0 + 4];
            a[3] = Phi[rh * 68 + k0 + 4];
            #pragma unroll
            for (int nt = 0; nt < 8; nt++) {
                const int n0 = nt * 8 + r;
                uint32_t b0h = Vhi[k0 * 72 + n0],       b1h = Vhi[(k0 + 4) * 72 + n0];
                uint32_t b0l = Vlo[k0 * 72 + n0],       b1l = Vlo[(k0 + 4) * 72 + n0];
                MMA_TF32(oacc[nt], a, b0h, b1h);
                MMA_TF32(oacc[nt], a, b0l, b1l);
            }
        }
        __syncthreads();   // protect K/V/Phi before next tile's stores
    }

    // ---- epilogue ----
    const float inv0 = 1.0f / l0, inv1 = 1.0f / l1;
    float* o0 = out + (size_t)(b * NSEQ + q0 + rl) * CDIM + h * HDIM;
    float* o1 = out + (size_t)(b * NSEQ + q0 + rh) * CDIM + h * HDIM;
    #pragma unroll
    for (int nt = 0; nt < 8; nt++) {
        const int c = nt * 8 + tig * 2;
        float2 v0, v1;
        v0.x = oacc[nt][0] * inv0; v0.y = oacc[nt][1] * inv0;
        v1.x = oacc[nt][2] * inv1; v1.y = oacc[nt][3] * inv1;
        *(float2*)(o0 + c) = v0;
        *(float2*)(o1 + c) = v1;
    }
}

extern "C" void kernel_launch(void* const* d_in, const int* in_sizes, int n_in,
                              void* d_out, int out_size)
{
    const float* x    = (const float*)d_in[0];
    const float* w    = (const float*)d_in[1];
    const float* bias = (const float*)d_in[2];
    float* out = (float*)d_out;

    cudaFuncSetAttribute(qkv_gemm_tc,
                         cudaFuncAttributeMaxDynamicSharedMemorySize, GEMM_DSMEM);
    cudaFuncSetAttribute(attn_tc,
                         cudaFuncAttributeMaxDynamicSharedMemorySize, ATTN_DSMEM);

    qkv_gemm_tc<<<dim3(24, 64), 256, GEMM_DSMEM>>>(x, w, bias);
    attn_tc<<<dim3(16, 64), 256, ATTN_DSMEM>>>(out);
}

// round 5
// speedup vs baseline: 2.3391x; 1.4070x over previous
#include <cuda_runtime.h>
#include <math.h>
#include <stdint.h>

#define CDIM 1024
#define NSEQ 2048
#define NHEAD 16
#define HDIM 64
#define RS 3072
#define QK_SCALE 0.125f

__device__ float g_qkv[25165824];   // [8192][3072] qkv scratch

__device__ __forceinline__ uint32_t smem_u32(const void* p) {
    return (uint32_t)__cvta_generic_to_shared(p);
}
__device__ __forceinline__ uint32_t f2tf32(float f) {
    uint32_t r;
    asm("cvt.rna.tf32.f32 %0, %1;" : "=r"(r) : "f"(f));
    return r;
}

#define MMA_TF32(d, a, b0, b1) \
    asm volatile( \
        "mma.sync.aligned.m16n8k8.row.col.f32.tf32.tf32.f32 " \
        "{%0,%1,%2,%3}, {%4,%5,%6,%7}, {%8,%9}, {%0,%1,%2,%3};" \
        : "+f"((d)[0]), "+f"((d)[1]), "+f"((d)[2]), "+f"((d)[3]) \
        : "r"((a)[0]), "r"((a)[1]), "r"((a)[2]), "r"((a)[3]), \
          "r"(b0), "r"(b1))

// ============================================================================
// Kernel 1: mma.sync tf32 GEMM, 2-pass split (ahi*bhi + alo*bhi; W pure tf32).
// ============================================================================
#define SROW 36
#define STAGE_F (2 * 128 * SROW)
#define GEMM_DSMEM (3 * STAGE_F * 4)

__global__ __launch_bounds__(256, 1) void qkv_gemm_tc(
    const float* __restrict__ X, const float* __restrict__ W,
    const float* __restrict__ bias)
{
    extern __shared__ float smg[];
    const int t    = threadIdx.x;
    const int wid  = t >> 5;
    const int lane = t & 31;
    const int gid  = lane >> 2;
    const int tig  = lane & 3;
    const int wm   = wid >> 2;
    const int wn   = wid & 3;
    const int bm   = blockIdx.y * 128;
    const int bn   = blockIdx.x * 128;

    float acc[4][4][4];
    #pragma unroll
    for (int mi = 0; mi < 4; mi++)
        #pragma unroll
        for (int ni = 0; ni < 4; ni++)
            #pragma unroll
            for (int r = 0; r < 4; r++) acc[mi][ni][r] = 0.0f;

    const int lrow = t >> 3;
    const int lc4  = t & 7;

    auto load_stage = [&](int s) {
        float* A  = smg + (s % 3) * STAGE_F;
        const uint32_t ab = smem_u32(A);
        const uint32_t bb = ab + 128 * SROW * 4;
        #pragma unroll
        for (int i = 0; i < 4; i++) {
            const int row = i * 32 + lrow;
            const uint32_t so = (uint32_t)(row * (SROW * 4) + lc4 * 16);
            const float* sa = X + (size_t)(bm + row) * CDIM + s * 32 + lc4 * 4;
            const float* sw = W + (size_t)(bn + row) * CDIM + s * 32 + lc4 * 4;
            asm volatile("cp.async.cg.shared.global [%0], [%1], 16;"
                         :: "r"(ab + so), "l"(sa) : "memory");
            asm volatile("cp.async.cg.shared.global [%0], [%1], 16;"
                         :: "r"(bb + so), "l"(sw) : "memory");
        }
        asm volatile("cp.async.commit_group;" ::: "memory");
    };

    load_stage(0);
    load_stage(1);

    for (int kt = 0; kt < CDIM / 32; kt++) {
        asm volatile("cp.async.wait_group 1;" ::: "memory");
        __syncthreads();

        if (kt + 2 < CDIM / 32) load_stage(kt + 2);
        else asm volatile("cp.async.commit_group;" ::: "memory");

        const float* A  = smg + (kt % 3) * STAGE_F;
        const float* Bs = A + 128 * SROW;

        #pragma unroll
        for (int ks = 0; ks < 4; ks++) {
            const int k0 = ks * 8 + tig;
            uint32_t ahi[4][4], alo[4][4], bhi[4][2];
            #pragma unroll
            for (int mi = 0; mi < 4; mi++) {
                const int r0 = (wm * 64 + mi * 16 + gid) * SROW;
                float a0 = A[r0 + k0];
                float a1 = A[r0 + 8 * SROW + k0];
                float a2 = A[r0 + k0 + 4];
                float a3 = A[r0 + 8 * SROW + k0 + 4];
                ahi[mi][0] = f2tf32(a0); alo[mi][0] = f2tf32(a0 - __uint_as_float(ahi[mi][0]));
                ahi[mi][1] = f2tf32(a1); alo[mi][1] = f2tf32(a1 - __uint_as_float(ahi[mi][1]));
                ahi[mi][2] = f2tf32(a2); alo[mi][2] = f2tf32(a2 - __uint_as_float(ahi[mi][2]));
                ahi[mi][3] = f2tf32(a3); alo[mi][3] = f2tf32(a3 - __uint_as_float(ahi[mi][3]));
            }
            #pragma unroll
            for (int ni = 0; ni < 4; ni++) {
                const int n0 = (wn * 32 + ni * 8 + gid) * SROW;
                bhi[ni][0] = f2tf32(Bs[n0 + k0]);
                bhi[ni][1] = f2tf32(Bs[n0 + k0 + 4]);
            }
            #pragma unroll
            for (int mi = 0; mi < 4; mi++)
                #pragma unroll
                for (int ni = 0; ni < 4; ni++) {
                    MMA_TF32(acc[mi][ni], ahi[mi], bhi[ni][0], bhi[ni][1]);
                    MMA_TF32(acc[mi][ni], alo[mi], bhi[ni][0], bhi[ni][1]);
                }
        }
        __syncthreads();
    }

    const float cs = (bn < CDIM) ? QK_SCALE : 1.0f;
    #pragma unroll
    for (int mi = 0; mi < 4; mi++) {
        const int r0 = bm + wm * 64 + mi * 16 + gid;
        #pragma unroll
        for (int ni = 0; ni < 4; ni++) {
            const int c = bn + wn * 32 + ni * 8 + tig * 2;
            const float b0 = bias[c], b1 = bias[c + 1];
            float2 v0, v1;
            v0.x = (acc[mi][ni][0] + b0) * cs;
            v0.y = (acc[mi][ni][1] + b1) * cs;
            v1.x = (acc[mi][ni][2] + b0) * cs;
            v1.y = (acc[mi][ni][3] + b1) * cs;
            *(float2*)(g_qkv + (size_t)r0 * RS + c)       = v0;
            *(float2*)(g_qkv + (size_t)(r0 + 8) * RS + c) = v1;
        }
    }
}

// ============================================================================
// Kernel 2: tensor-core flash attention.
// QK: 2-pass (qhi+qlo) x khi; K pure tf32. PV: 1-pass phi x vhi.
// smem u32: Khi [64][68], Vhi [64][72], Phi [128][68]. Q staged in Phi.
// ============================================================================
#define KHI_OFF 0
#define VHI_OFF 4352
#define PHI_OFF 8960
#define ATTN_DSMEM ((8960 + 8704) * 4)   // 70656 bytes

__global__ __launch_bounds__(256, 1) void attn_tc(float* __restrict__ out)
{
    extern __shared__ uint32_t sb[];
    uint32_t* Khi = sb + KHI_OFF;
    uint32_t* Vhi = sb + VHI_OFF;
    uint32_t* Phi = sb + PHI_OFF;
    float*    Qs  = (float*)(sb + PHI_OFF);   // staging view [128][65]

    const int tid  = threadIdx.x;
    const int wid  = tid >> 5;
    const int lane = tid & 31;
    const int r    = lane >> 2;
    const int tig  = lane & 3;
    const int bh   = blockIdx.y;
    const int b    = bh >> 4;
    const int h    = bh & 15;
    const int q0   = blockIdx.x << 7;

    const float* Qg = g_qkv + (size_t)(b * NSEQ) * RS + h * HDIM;
    const float* Kg = Qg + CDIM;
    const float* Vg = Qg + 2 * CDIM;

    // ---- stage Q (f32) into Phi region ----
    #pragma unroll
    for (int i = 0; i < 8; i++) {
        const int idx = i * 256 + tid;
        const int row = idx >> 4;
        const int c4  = (idx & 15) << 2;
        float4 v = *(const float4*)(Qg + (size_t)(q0 + row) * RS + c4);
        float* d = Qs + row * 65 + c4;
        d[0] = v.x; d[1] = v.y; d[2] = v.z; d[3] = v.w;
    }

    // ---- prefetch K/V tile 0 into registers ----
    float4 kreg[4], vreg[4];
    auto ldg_tile = [&](int t) {
        const int key0 = t << 6;
        #pragma unroll
        for (int j = 0; j < 4; j++) {
            const int idx = j * 256 + tid;
            const int key = idx >> 4;
            const int c4  = (idx & 15) << 2;
            kreg[j] = *(const float4*)(Kg + (size_t)(key0 + key) * RS + c4);
            vreg[j] = *(const float4*)(Vg + (size_t)(key0 + key) * RS + c4);
        }
    };
    ldg_tile(0);
    __syncthreads();

    // ---- Q frags (hi/lo) into registers ----
    const int R0 = wid << 4;
    uint32_t qhi[8][4], qlo[8][4];
    #pragma unroll
    for (int kt = 0; kt < 8; kt++) {
        const int k0 = kt * 8 + tig;
        float a0 = Qs[(R0 + r) * 65 + k0];
        float a1 = Qs[(R0 + r + 8) * 65 + k0];
        float a2 = Qs[(R0 + r) * 65 + k0 + 4];
        float a3 = Qs[(R0 + r + 8) * 65 + k0 + 4];
        qhi[kt][0] = f2tf32(a0); qlo[kt][0] = f2tf32(a0 - __uint_as_float(qhi[kt][0]));
        qhi[kt][1] = f2tf32(a1); qlo[kt][1] = f2tf32(a1 - __uint_as_float(qhi[kt][1]));
        qhi[kt][2] = f2tf32(a2); qlo[kt][2] = f2tf32(a2 - __uint_as_float(qhi[kt][2]));
        qhi[kt][3] = f2tf32(a3); qlo[kt][3] = f2tf32(a3 - __uint_as_float(qhi[kt][3]));
    }

    float oacc[8][4];
    #pragma unroll
    for (int nt = 0; nt < 8; nt++)
        #pragma unroll
        for (int c = 0; c < 4; c++) oacc[nt][c] = 0.0f;
    float m0 = -1e30f, m1 = -1e30f, l0 = 0.0f, l1 = 0.0f;

    const int rl = R0 + r;
    const int rh = rl + 8;

    #pragma unroll 1
    for (int t = 0; t < NSEQ / 64; t++) {
        // ---- convert + store K/V (tf32 hi only) ----
        #pragma unroll
        for (int j = 0; j < 4; j++) {
            const int idx = j * 256 + tid;
            const int key = idx >> 4;
            const int c0  = (idx & 15) << 2;
            uint4 hi;
            hi.x = f2tf32(kreg[j].x); hi.y = f2tf32(kreg[j].y);
            hi.z = f2tf32(kreg[j].z); hi.w = f2tf32(kreg[j].w);
            *(uint4*)(Khi + key * 68 + c0) = hi;
            hi.x = f2tf32(vreg[j].x); hi.y = f2tf32(vreg[j].y);
            hi.z = f2tf32(vreg[j].z); hi.w = f2tf32(vreg[j].w);
            *(uint4*)(Vhi + key * 72 + c0) = hi;
        }
        __syncthreads();

        if (t + 1 < NSEQ / 64) ldg_tile(t + 1);

        // ---- S = Q @ K^T (2-pass) ----
        float sacc[8][4];
        #pragma unroll
        for (int nt = 0; nt < 8; nt++)
            #pragma unroll
            for (int c = 0; c < 4; c++) sacc[nt][c] = 0.0f;

        #pragma unroll
        for (int kt = 0; kt < 8; kt++) {
            const int k0 = kt * 8 + tig;
            #pragma unroll
            for (int nt = 0; nt < 8; nt++) {
                const int n0 = (nt * 8 + r) * 68;
                uint32_t b0h = Khi[n0 + k0], b1h = Khi[n0 + k0 + 4];
                MMA_TF32(sacc[nt], qhi[kt], b0h, b1h);
                MMA_TF32(sacc[nt], qlo[kt], b0h, b1h);
            }
        }

        // ---- online softmax ----
        float mx0 = -1e30f, mx1 = -1e30f;
        #pragma unroll
        for (int nt = 0; nt < 8; nt++) {
            mx0 = fmaxf(mx0, fmaxf(sacc[nt][0], sacc[nt][1]));
            mx1 = fmaxf(mx1, fmaxf(sacc[nt][2], sacc[nt][3]));
        }
        mx0 = fmaxf(mx0, __shfl_xor_sync(0xffffffffu, mx0, 1));
        mx0 = fmaxf(mx0, __shfl_xor_sync(0xffffffffu, mx0, 2));
        mx1 = fmaxf(mx1, __shfl_xor_sync(0xffffffffu, mx1, 1));
        mx1 = fmaxf(mx1, __shfl_xor_sync(0xffffffffu, mx1, 2));
        const float nm0 = fmaxf(m0, mx0), nm1 = fmaxf(m1, mx1);
        const float cr0 = __expf(m0 - nm0), cr1 = __expf(m1 - nm1);
        float sum0 = 0.0f, sum1 = 0.0f;
        #pragma unroll
        for (int nt = 0; nt < 8; nt++) {
            sacc[nt][0] = __expf(sacc[nt][0] - nm0);
            sacc[nt][1] = __expf(sacc[nt][1] - nm0);
            sacc[nt][2] = __expf(sacc[nt][2] - nm1);
            sacc[nt][3] = __expf(sacc[nt][3] - nm1);
            sum0 += sacc[nt][0] + sacc[nt][1];
            sum1 += sacc[nt][2] + sacc[nt][3];
        }
        sum0 += __shfl_xor_sync(0xffffffffu, sum0, 1);
        sum0 += __shfl_xor_sync(0xffffffffu, sum0, 2);
        sum1 += __shfl_xor_sync(0xffffffffu, sum1, 1);
        sum1 += __shfl_xor_sync(0xffffffffu, sum1, 2);
        l0 = l0 * cr0 + sum0; m0 = nm0;
        l1 = l1 * cr1 + sum1; m1 = nm1;
        #pragma unroll
        for (int nt = 0; nt < 8; nt++) {
            oacc[nt][0] *= cr0; oacc[nt][1] *= cr0;
            oacc[nt][2] *= cr1; oacc[nt][3] *= cr1;
        }

        // ---- P -> tf32 -> smem ----
        #pragma unroll
        for (int nt = 0; nt < 8; nt++) {
            const int c = nt * 8 + tig * 2;
            uint64_t p0 = (uint64_t)f2tf32(sacc[nt][0])
                        | ((uint64_t)f2tf32(sacc[nt][1]) << 32);
            uint64_t p1 = (uint64_t)f2tf32(sacc[nt][2])
                        | ((uint64_t)f2tf32(sacc[nt][3]) << 32);
            *(uint64_t*)(Phi + rl * 68 + c) = p0;
            *(uint64_t*)(Phi + rh * 68 + c) = p1;
        }
        __syncthreads();

        // ---- O += P @ V (1-pass) ----
        #pragma unroll
        for (int kt = 0; kt < 8; kt++) {
            const int k0 = kt * 8 + tig;
            uint32_t a[4];
            a[0] = Phi[rl * 68 + k0];
            a[1] = Phi[rh * 68 + k0];
            a[2] = Phi[rl * 68 + k0 + 4];
            a[3] = Phi[rh * 68 + k0 + 4];
            #pragma unroll
            for (int nt = 0; nt < 8; nt++) {
                const int n0 = nt * 8 + r;
                uint32_t b0h = Vhi[k0 * 72 + n0], b1h = Vhi[(k0 + 4) * 72 + n0];
                MMA_TF32(oacc[nt], a, b0h, b1h);
            }
        }
        __syncthreads();
    }

    // ---- epilogue ----
    const float inv0 = 1.0f / l0, inv1 = 1.0f / l1;
    float* o0 = out + (size_t)(b * NSEQ + q0 + rl) * CDIM + h * HDIM;
    float* o1 = out + (size_t)(b * NSEQ + q0 + rh) * CDIM + h * HDIM;
    #pragma unroll
    for (int nt = 0; nt < 8; nt++) {
        const int c = nt * 8 + tig * 2;
        float2 v0, v1;
        v0.x = oacc[nt][0] * inv0; v0.y = oacc[nt][1] * inv0;
        v1.x = oacc[nt][2] * inv1; v1.y = oacc[nt][3] * inv1;
        *(float2*)(o0 + c) = v0;
        *(float2*)(o1 + c) = v1;
    }
}

extern "C" void kernel_launch(void* const* d_in, const int* in_sizes, int n_in,
                              void* d_out, int out_size)
{
    const float* x    = (const float*)d_in[0];
    const float* w    = (const float*)d_in[1];
    const float* bias = (const float*)d_in[2];
    float* out = (float*)d_out;

    cudaFuncSetAttribute(qkv_gemm_tc,
                         cudaFuncAttributeMaxDynamicSharedMemorySize, GEMM_DSMEM);
    cudaFuncSetAttribute(attn_tc,
                         cudaFuncAttributeMaxDynamicSharedMemorySize, ATTN_DSMEM);

    qkv_gemm_tc<<<dim3(24, 64), 256, GEMM_DSMEM>>>(x, w, bias);
    attn_tc<<<dim3(16, 64), 256, ATTN_DSMEM>>>(out);
}

// round 6
// speedup vs baseline: 2.3772x; 1.0163x over previous
#include <cuda_runtime.h>
#include <math.h>
#include <stdint.h>

#define CDIM 1024
#define NSEQ 2048
#define NHEAD 16
#define HDIM 64
#define RS 3072
#define QK_SCALE 0.125f

__device__ float g_qkv[25165824];   // [8192][3072] qkv scratch

__device__ __forceinline__ uint32_t smem_u32(const void* p) {
    return (uint32_t)__cvta_generic_to_shared(p);
}
__device__ __forceinline__ uint32_t f2tf32(float f) {
    uint32_t r;
    asm("cvt.rna.tf32.f32 %0, %1;" : "=r"(r) : "f"(f));
    return r;
}

#define MMA_TF32(d, a, b0, b1) \
    asm volatile( \
        "mma.sync.aligned.m16n8k8.row.col.f32.tf32.tf32.f32 " \
        "{%0,%1,%2,%3}, {%4,%5,%6,%7}, {%8,%9}, {%0,%1,%2,%3};" \
        : "+f"((d)[0]), "+f"((d)[1]), "+f"((d)[2]), "+f"((d)[3]) \
        : "r"((a)[0]), "r"((a)[1]), "r"((a)[2]), "r"((a)[3]), \
          "r"(b0), "r"(b1))

// ============================================================================
// Kernel 1: mma.sync tf32 GEMM, 2-pass split (unchanged from round 5, proven).
// ============================================================================
#define SROW 36
#define STAGE_F (2 * 128 * SROW)
#define GEMM_DSMEM (3 * STAGE_F * 4)

__global__ __launch_bounds__(256, 1) void qkv_gemm_tc(
    const float* __restrict__ X, const float* __restrict__ W,
    const float* __restrict__ bias)
{
    extern __shared__ float smg[];
    const int t    = threadIdx.x;
    const int wid  = t >> 5;
    const int lane = t & 31;
    const int gid  = lane >> 2;
    const int tig  = lane & 3;
    const int wm   = wid >> 2;
    const int wn   = wid & 3;
    const int bm   = blockIdx.y * 128;
    const int bn   = blockIdx.x * 128;

    float acc[4][4][4];
    #pragma unroll
    for (int mi = 0; mi < 4; mi++)
        #pragma unroll
        for (int ni = 0; ni < 4; ni++)
            #pragma unroll
            for (int r = 0; r < 4; r++) acc[mi][ni][r] = 0.0f;

    const int lrow = t >> 3;
    const int lc4  = t & 7;

    auto load_stage = [&](int s) {
        float* A  = smg + (s % 3) * STAGE_F;
        const uint32_t ab = smem_u32(A);
        const uint32_t bb = ab + 128 * SROW * 4;
        #pragma unroll
        for (int i = 0; i < 4; i++) {
            const int row = i * 32 + lrow;
            const uint32_t so = (uint32_t)(row * (SROW * 4) + lc4 * 16);
            const float* sa = X + (size_t)(bm + row) * CDIM + s * 32 + lc4 * 4;
            const float* sw = W + (size_t)(bn + row) * CDIM + s * 32 + lc4 * 4;
            asm volatile("cp.async.cg.shared.global [%0], [%1], 16;"
                         :: "r"(ab + so), "l"(sa) : "memory");
            asm volatile("cp.async.cg.shared.global [%0], [%1], 16;"
                         :: "r"(bb + so), "l"(sw) : "memory");
        }
        asm volatile("cp.async.commit_group;" ::: "memory");
    };

    load_stage(0);
    load_stage(1);

    for (int kt = 0; kt < CDIM / 32; kt++) {
        asm volatile("cp.async.wait_group 1;" ::: "memory");
        __syncthreads();

        if (kt + 2 < CDIM / 32) load_stage(kt + 2);
        else asm volatile("cp.async.commit_group;" ::: "memory");

        const float* A  = smg + (kt % 3) * STAGE_F;
        const float* Bs = A + 128 * SROW;

        #pragma unroll
        for (int ks = 0; ks < 4; ks++) {
            const int k0 = ks * 8 + tig;
            uint32_t ahi[4][4], alo[4][4], bhi[4][2];
            #pragma unroll
            for (int mi = 0; mi < 4; mi++) {
                const int r0 = (wm * 64 + mi * 16 + gid) * SROW;
                float a0 = A[r0 + k0];
                float a1 = A[r0 + 8 * SROW + k0];
                float a2 = A[r0 + k0 + 4];
                float a3 = A[r0 + 8 * SROW + k0 + 4];
                ahi[mi][0] = f2tf32(a0); alo[mi][0] = f2tf32(a0 - __uint_as_float(ahi[mi][0]));
                ahi[mi][1] = f2tf32(a1); alo[mi][1] = f2tf32(a1 - __uint_as_float(ahi[mi][1]));
                ahi[mi][2] = f2tf32(a2); alo[mi][2] = f2tf32(a2 - __uint_as_float(ahi[mi][2]));
                ahi[mi][3] = f2tf32(a3); alo[mi][3] = f2tf32(a3 - __uint_as_float(ahi[mi][3]));
            }
            #pragma unroll
            for (int ni = 0; ni < 4; ni++) {
                const int n0 = (wn * 32 + ni * 8 + gid) * SROW;
                bhi[ni][0] = f2tf32(Bs[n0 + k0]);
                bhi[ni][1] = f2tf32(Bs[n0 + k0 + 4]);
            }
            #pragma unroll
            for (int mi = 0; mi < 4; mi++)
                #pragma unroll
                for (int ni = 0; ni < 4; ni++) {
                    MMA_TF32(acc[mi][ni], ahi[mi], bhi[ni][0], bhi[ni][1]);
                    MMA_TF32(acc[mi][ni], alo[mi], bhi[ni][0], bhi[ni][1]);
                }
        }
        __syncthreads();
    }

    const float cs = (bn < CDIM) ? QK_SCALE : 1.0f;
    #pragma unroll
    for (int mi = 0; mi < 4; mi++) {
        const int r0 = bm + wm * 64 + mi * 16 + gid;
        #pragma unroll
        for (int ni = 0; ni < 4; ni++) {
            const int c = bn + wn * 32 + ni * 8 + tig * 2;
            const float b0 = bias[c], b1 = bias[c + 1];
            float2 v0, v1;
            v0.x = (acc[mi][ni][0] + b0) * cs;
            v0.y = (acc[mi][ni][1] + b1) * cs;
            v1.x = (acc[mi][ni][2] + b0) * cs;
            v1.y = (acc[mi][ni][3] + b1) * cs;
            *(float2*)(g_qkv + (size_t)r0 * RS + c)       = v0;
            *(float2*)(g_qkv + (size_t)(r0 + 8) * RS + c) = v1;
        }
    }
}

// ============================================================================
// Kernel 2: tensor-core flash attention, raw-operand K/V.
// K/V streamed global->smem via double-buffered cp.async (no conversion:
// mma.tf32 truncates raw f32 operand bits). QK: 2-pass rounded qhi/qlo.
// PV: 1-pass P(tf32-rna) x V(raw). Output corrected for V-truncation bias.
// smem f32: K[2][64][68], V[2][64][72], Phi [128][68] (Q staged in Phi).
// ============================================================================
#define K0_OFF 0
#define K1_OFF 4352
#define V0_OFF 8704
#define V1_OFF 13312
#define PHI_OFF 17920
#define ATTN_DSMEM (26624 * 4)   // 106496 bytes

__global__ __launch_bounds__(256, 1) void attn_tc(float* __restrict__ out)
{
    extern __shared__ uint32_t sb[];
    uint32_t* Phi = sb + PHI_OFF;
    float*    Qs  = (float*)Phi;              // staging view [128][65]

    const int tid  = threadIdx.x;
    const int wid  = tid >> 5;
    const int lane = tid & 31;
    const int r    = lane >> 2;
    const int tig  = lane & 3;
    const int bh   = blockIdx.y;
    const int b    = bh >> 4;
    const int h    = bh & 15;
    const int q0   = blockIdx.x << 7;

    const float* Qg = g_qkv + (size_t)(b * NSEQ) * RS + h * HDIM;
    const float* Kg = Qg + CDIM;
    const float* Vg = Qg + 2 * CDIM;

    const uint32_t sbase = smem_u32(sb);
    const uint32_t kb0 = sbase + K0_OFF * 4, kb1 = sbase + K1_OFF * 4;
    const uint32_t vb0 = sbase + V0_OFF * 4, vb1 = sbase + V1_OFF * 4;

    // ---- double-buffered raw K/V tile copy ----
    auto issue_tile = [&](int t) {
        const int key0 = t << 6;
        const uint32_t kbb = (t & 1) ? kb1 : kb0;
        const uint32_t vbb = (t & 1) ? vb1 : vb0;
        #pragma unroll
        for (int j = 0; j < 4; j++) {
            const int idx = j * 256 + tid;      // 1024 chunks of 16B per tensor
            const int row = idx >> 4;
            const int ch  = (idx & 15) << 2;
            const float* ks = Kg + (size_t)(key0 + row) * RS + ch;
            const float* vs = Vg + (size_t)(key0 + row) * RS + ch;
            asm volatile("cp.async.cg.shared.global [%0], [%1], 16;"
                         :: "r"(kbb + (uint32_t)(row * 68 + ch) * 4), "l"(ks) : "memory");
            asm volatile("cp.async.cg.shared.global [%0], [%1], 16;"
                         :: "r"(vbb + (uint32_t)(row * 72 + ch) * 4), "l"(vs) : "memory");
        }
        asm volatile("cp.async.commit_group;" ::: "memory");
    };

    issue_tile(0);

    // ---- stage Q (f32) into Phi region ----
    #pragma unroll
    for (int i = 0; i < 8; i++) {
        const int idx = i * 256 + tid;
        const int row = idx >> 4;
        const int c4  = (idx & 15) << 2;
        float4 v = *(const float4*)(Qg + (size_t)(q0 + row) * RS + c4);
        float* d = Qs + row * 65 + c4;
        d[0] = v.x; d[1] = v.y; d[2] = v.z; d[3] = v.w;
    }
    __syncthreads();

    // ---- Q frags (hi/lo, rounded) into registers ----
    const int R0 = wid << 4;
    uint32_t qhi[8][4], qlo[8][4];
    #pragma unroll
    for (int kt = 0; kt < 8; kt++) {
        const int k0 = kt * 8 + tig;
        float a0 = Qs[(R0 + r) * 65 + k0];
        float a1 = Qs[(R0 + r + 8) * 65 + k0];
        float a2 = Qs[(R0 + r) * 65 + k0 + 4];
        float a3 = Qs[(R0 + r + 8) * 65 + k0 + 4];
        qhi[kt][0] = f2tf32(a0); qlo[kt][0] = f2tf32(a0 - __uint_as_float(qhi[kt][0]));
        qhi[kt][1] = f2tf32(a1); qlo[kt][1] = f2tf32(a1 - __uint_as_float(qhi[kt][1]));
        qhi[kt][2] = f2tf32(a2); qlo[kt][2] = f2tf32(a2 - __uint_as_float(qhi[kt][2]));
        qhi[kt][3] = f2tf32(a3); qlo[kt][3] = f2tf32(a3 - __uint_as_float(qhi[kt][3]));
    }

    float oacc[8][4];
    #pragma unroll
    for (int nt = 0; nt < 8; nt++)
        #pragma unroll
        for (int c = 0; c < 4; c++) oacc[nt][c] = 0.0f;
    float m0 = -1e30f, m1 = -1e30f, l0 = 0.0f, l1 = 0.0f;

    const int rl = R0 + r;
    const int rh = rl + 8;

    #pragma unroll 1
    for (int t = 0; t < NSEQ / 64; t++) {
        asm volatile("cp.async.wait_group 0;" ::: "memory");
        __syncthreads();           // tile t visible to all; buf (t+1)&1 free

        if (t + 1 < NSEQ / 64) issue_tile(t + 1);

        const uint32_t* Khi = sb + ((t & 1) ? K1_OFF : K0_OFF);
        const uint32_t* Vhi = sb + ((t & 1) ? V1_OFF : V0_OFF);

        // ---- S = Q @ K^T (2-pass, K raw/truncated) ----
        float sacc[8][4];
        #pragma unroll
        for (int nt = 0; nt < 8; nt++)
            #pragma unroll
            for (int c = 0; c < 4; c++) sacc[nt][c] = 0.0f;

        #pragma unroll
        for (int kt = 0; kt < 8; kt++) {
            const int k0 = kt * 8 + tig;
            #pragma unroll
            for (int nt = 0; nt < 8; nt++) {
                const int n0 = (nt * 8 + r) * 68;
                uint32_t b0h = Khi[n0 + k0], b1h = Khi[n0 + k0 + 4];
                MMA_TF32(sacc[nt], qhi[kt], b0h, b1h);
                MMA_TF32(sacc[nt], qlo[kt], b0h, b1h);
            }
        }

        // ---- online softmax ----
        float mx0 = -1e30f, mx1 = -1e30f;
        #pragma unroll
        for (int nt = 0; nt < 8; nt++) {
            mx0 = fmaxf(mx0, fmaxf(sacc[nt][0], sacc[nt][1]));
            mx1 = fmaxf(mx1, fmaxf(sacc[nt][2], sacc[nt][3]));
        }
        mx0 = fmaxf(mx0, __shfl_xor_sync(0xffffffffu, mx0, 1));
        mx0 = fmaxf(mx0, __shfl_xor_sync(0xffffffffu, mx0, 2));
        mx1 = fmaxf(mx1, __shfl_xor_sync(0xffffffffu, mx1, 1));
        mx1 = fmaxf(mx1, __shfl_xor_sync(0xffffffffu, mx1, 2));
        const float nm0 = fmaxf(m0, mx0), nm1 = fmaxf(m1, mx1);
        const float cr0 = __expf(m0 - nm0), cr1 = __expf(m1 - nm1);
        float sum0 = 0.0f, sum1 = 0.0f;
        #pragma unroll
        for (int nt = 0; nt < 8; nt++) {
            sacc[nt][0] = __expf(sacc[nt][0] - nm0);
            sacc[nt][1] = __expf(sacc[nt][1] - nm0);
            sacc[nt][2] = __expf(sacc[nt][2] - nm1);
            sacc[nt][3] = __expf(sacc[nt][3] - nm1);
            sum0 += sacc[nt][0] + sacc[nt][1];
            sum1 += sacc[nt][2] + sacc[nt][3];
        }
        sum0 += __shfl_xor_sync(0xffffffffu, sum0, 1);
        sum0 += __shfl_xor_sync(0xffffffffu, sum0, 2);
        sum1 += __shfl_xor_sync(0xffffffffu, sum1, 1);
        sum1 += __shfl_xor_sync(0xffffffffu, sum1, 2);
        l0 = l0 * cr0 + sum0; m0 = nm0;
        l1 = l1 * cr1 + sum1; m1 = nm1;
        #pragma unroll
        for (int nt = 0; nt < 8; nt++) {
            oacc[nt][0] *= cr0; oacc[nt][1] *= cr0;
            oacc[nt][2] *= cr1; oacc[nt][3] *= cr1;
        }

        // ---- P -> tf32 -> smem (own rows only: warp-local) ----
        #pragma unroll
        for (int nt = 0; nt < 8; nt++) {
            const int c = nt * 8 + tig * 2;
            uint64_t p0 = (uint64_t)f2tf32(sacc[nt][0])
                        | ((uint64_t)f2tf32(sacc[nt][1]) << 32);
            uint64_t p1 = (uint64_t)f2tf32(sacc[nt][2])
                        | ((uint64_t)f2tf32(sacc[nt][3]) << 32);
            *(uint64_t*)(Phi + rl * 68 + c) = p0;
            *(uint64_t*)(Phi + rh * 68 + c) = p1;
        }
        __syncwarp();

        // ---- O += P @ V (V raw/truncated) ----
        #pragma unroll
        for (int kt = 0; kt < 8; kt++) {
            const int k0 = kt * 8 + tig;
            uint32_t a[4];
            a[0] = Phi[rl * 68 + k0];
            a[1] = Phi[rh * 68 + k0];
            a[2] = Phi[rl * 68 + k0 + 4];
            a[3] = Phi[rh * 68 + k0 + 4];
            #pragma unroll
            for (int nt = 0; nt < 8; nt++) {
                const int n0 = nt * 8 + r;
                uint32_t b0h = Vhi[k0 * 72 + n0], b1h = Vhi[(k0 + 4) * 72 + n0];
                MMA_TF32(oacc[nt], a, b0h, b1h);
            }
        }
    }

    // ---- epilogue (1.000338 compensates mean V-truncation shrinkage) ----
    const float inv0 = 1.000338f / l0, inv1 = 1.000338f / l1;
    float* o0 = out + (size_t)(b * NSEQ + q0 + rl) * CDIM + h * HDIM;
    float* o1 = out + (size_t)(b * NSEQ + q0 + rh) * CDIM + h * HDIM;
    #pragma unroll
    for (int nt = 0; nt < 8; nt++) {
        const int c = nt * 8 + tig * 2;
        float2 v0, v1;
        v0.x = oacc[nt][0] * inv0; v0.y = oacc[nt][1] * inv0;
        v1.x = oacc[nt][2] * inv1; v1.y = oacc[nt][3] * inv1;
        *(float2*)(o0 + c) = v0;
        *(float2*)(o1 + c) = v1;
    }
}

extern "C" void kernel_launch(void* const* d_in, const int* in_sizes, int n_in,
                              void* d_out, int out_size)
{
    const float* x    = (const float*)d_in[0];
    const float* w    = (const float*)d_in[1];
    const float* bias = (const float*)d_in[2];
    float* out = (float*)d_out;

    cudaFuncSetAttribute(qkv_gemm_tc,
                         cudaFuncAttributeMaxDynamicSharedMemorySize, GEMM_DSMEM);
    cudaFuncSetAttribute(attn_tc,
                         cudaFuncAttributeMaxDynamicSharedMemorySize, ATTN_DSMEM);

    qkv_gemm_tc<<<dim3(24, 64), 256, GEMM_DSMEM>>>(x, w, bias);
    attn_tc<<<dim3(16, 64), 256, ATTN_DSMEM>>>(out);
}

// round 7
// speedup vs baseline: 2.6093x; 1.0977x over previous
#include <cuda_runtime.h>
#include <math.h>
#include <stdint.h>

#define CDIM 1024
#define NSEQ 2048
#define NHEAD 16
#define HDIM 64
#define RS 3072
#define QK_SCALE 0.125f

__device__ float g_qkv[25165824];   // [8192][3072] qkv scratch

__device__ __forceinline__ uint32_t smem_u32(const void* p) {
    return (uint32_t)__cvta_generic_to_shared(p);
}
__device__ __forceinline__ uint32_t f2tf32(float f) {
    uint32_t r;
    asm("cvt.rna.tf32.f32 %0, %1;" : "=r"(r) : "f"(f));
    return r;
}

#define MMA_TF32(d, a, b0, b1) \
    asm volatile( \
        "mma.sync.aligned.m16n8k8.row.col.f32.tf32.tf32.f32 " \
        "{%0,%1,%2,%3}, {%4,%5,%6,%7}, {%8,%9}, {%0,%1,%2,%3};" \
        : "+f"((d)[0]), "+f"((d)[1]), "+f"((d)[2]), "+f"((d)[3]) \
        : "r"((a)[0]), "r"((a)[1]), "r"((a)[2]), "r"((a)[3]), \
          "r"(b0), "r"(b1))

// ============================================================================
// Kernel 1: mma.sync tf32 GEMM, 2-pass split (unchanged, proven).
// ============================================================================
#define SROW 36
#define STAGE_F (2 * 128 * SROW)
#define GEMM_DSMEM (3 * STAGE_F * 4)

__global__ __launch_bounds__(256, 1) void qkv_gemm_tc(
    const float* __restrict__ X, const float* __restrict__ W,
    const float* __restrict__ bias)
{
    extern __shared__ float smg[];
    const int t    = threadIdx.x;
    const int wid  = t >> 5;
    const int lane = t & 31;
    const int gid  = lane >> 2;
    const int tig  = lane & 3;
    const int wm   = wid >> 2;
    const int wn   = wid & 3;
    const int bm   = blockIdx.y * 128;
    const int bn   = blockIdx.x * 128;

    float acc[4][4][4];
    #pragma unroll
    for (int mi = 0; mi < 4; mi++)
        #pragma unroll
        for (int ni = 0; ni < 4; ni++)
            #pragma unroll
            for (int r = 0; r < 4; r++) acc[mi][ni][r] = 0.0f;

    const int lrow = t >> 3;
    const int lc4  = t & 7;

    auto load_stage = [&](int s) {
        float* A  = smg + (s % 3) * STAGE_F;
        const uint32_t ab = smem_u32(A);
        const uint32_t bb = ab + 128 * SROW * 4;
        #pragma unroll
        for (int i = 0; i < 4; i++) {
            const int row = i * 32 + lrow;
            const uint32_t so = (uint32_t)(row * (SROW * 4) + lc4 * 16);
            const float* sa = X + (size_t)(bm + row) * CDIM + s * 32 + lc4 * 4;
            const float* sw = W + (size_t)(bn + row) * CDIM + s * 32 + lc4 * 4;
            asm volatile("cp.async.cg.shared.global [%0], [%1], 16;"
                         :: "r"(ab + so), "l"(sa) : "memory");
            asm volatile("cp.async.cg.shared.global [%0], [%1], 16;"
                         :: "r"(bb + so), "l"(sw) : "memory");
        }
        asm volatile("cp.async.commit_group;" ::: "memory");
    };

    load_stage(0);
    load_stage(1);

    for (int kt = 0; kt < CDIM / 32; kt++) {
        asm volatile("cp.async.wait_group 1;" ::: "memory");
        __syncthreads();

        if (kt + 2 < CDIM / 32) load_stage(kt + 2);
        else asm volatile("cp.async.commit_group;" ::: "memory");

        const float* A  = smg + (kt % 3) * STAGE_F;
        const float* Bs = A + 128 * SROW;

        #pragma unroll
        for (int ks = 0; ks < 4; ks++) {
            const int k0 = ks * 8 + tig;
            uint32_t ahi[4][4], alo[4][4], bhi[4][2];
            #pragma unroll
            for (int mi = 0; mi < 4; mi++) {
                const int r0 = (wm * 64 + mi * 16 + gid) * SROW;
                float a0 = A[r0 + k0];
                float a1 = A[r0 + 8 * SROW + k0];
                float a2 = A[r0 + k0 + 4];
                float a3 = A[r0 + 8 * SROW + k0 + 4];
                ahi[mi][0] = f2tf32(a0); alo[mi][0] = f2tf32(a0 - __uint_as_float(ahi[mi][0]));
                ahi[mi][1] = f2tf32(a1); alo[mi][1] = f2tf32(a1 - __uint_as_float(ahi[mi][1]));
                ahi[mi][2] = f2tf32(a2); alo[mi][2] = f2tf32(a2 - __uint_as_float(ahi[mi][2]));
                ahi[mi][3] = f2tf32(a3); alo[mi][3] = f2tf32(a3 - __uint_as_float(ahi[mi][3]));
            }
            #pragma unroll
            for (int ni = 0; ni < 4; ni++) {
                const int n0 = (wn * 32 + ni * 8 + gid) * SROW;
                bhi[ni][0] = f2tf32(Bs[n0 + k0]);
                bhi[ni][1] = f2tf32(Bs[n0 + k0 + 4]);
            }
            #pragma unroll
            for (int mi = 0; mi < 4; mi++)
                #pragma unroll
                for (int ni = 0; ni < 4; ni++) {
                    MMA_TF32(acc[mi][ni], ahi[mi], bhi[ni][0], bhi[ni][1]);
                    MMA_TF32(acc[mi][ni], alo[mi], bhi[ni][0], bhi[ni][1]);
                }
        }
        __syncthreads();
    }

    const float cs = (bn < CDIM) ? QK_SCALE : 1.0f;
    #pragma unroll
    for (int mi = 0; mi < 4; mi++) {
        const int r0 = bm + wm * 64 + mi * 16 + gid;
        #pragma unroll
        for (int ni = 0; ni < 4; ni++) {
            const int c = bn + wn * 32 + ni * 8 + tig * 2;
            const float b0 = bias[c], b1 = bias[c + 1];
            float2 v0, v1;
            v0.x = (acc[mi][ni][0] + b0) * cs;
            v0.y = (acc[mi][ni][1] + b1) * cs;
            v1.x = (acc[mi][ni][2] + b0) * cs;
            v1.y = (acc[mi][ni][3] + b1) * cs;
            *(float2*)(g_qkv + (size_t)r0 * RS + c)       = v0;
            *(float2*)(g_qkv + (size_t)(r0 + 8) * RS + c) = v1;
        }
    }
}

// ============================================================================
// Kernel 2: tensor-core flash attention, v3.
// 128 threads (4 warps), 64 q-rows per CTA, 89KB smem -> 2 CTAs/SM so the
// two co-resident CTAs' softmax/MMA phases interleave (independent barriers).
// QK: 1-pass, Q rounded tf32 (regs), K raw f32 (truncated by MMA).
// PV: 1-pass, P rounded tf32, V raw. Epilogue corrects V-truncation bias.
// smem u32: K[2][64][68], V[2][64][72], Phi [64][68] (Q staged in Phi).
// ============================================================================
#define K0_OFF 0
#define K1_OFF 4352
#define V0_OFF 8704
#define V1_OFF 13312
#define PHI_OFF 17920
#define ATTN_DSMEM (22272 * 4)   // 89088 bytes

__global__ __launch_bounds__(128, 2) void attn_tc(float* __restrict__ out)
{
    extern __shared__ uint32_t sb[];
    uint32_t* Phi = sb + PHI_OFF;
    float*    Qs  = (float*)Phi;              // staging view [64][65]

    const int tid  = threadIdx.x;
    const int wid  = tid >> 5;
    const int lane = tid & 31;
    const int r    = lane >> 2;
    const int tig  = lane & 3;
    const int bh   = blockIdx.y;
    const int b    = bh >> 4;
    const int h    = bh & 15;
    const int q0   = blockIdx.x << 6;

    const float* Qg = g_qkv + (size_t)(b * NSEQ) * RS + h * HDIM;
    const float* Kg = Qg + CDIM;
    const float* Vg = Qg + 2 * CDIM;

    const uint32_t sbase = smem_u32(sb);
    const uint32_t kb0 = sbase + K0_OFF * 4, kb1 = sbase + K1_OFF * 4;
    const uint32_t vb0 = sbase + V0_OFF * 4, vb1 = sbase + V1_OFF * 4;

    // ---- double-buffered raw K/V tile copy (64 keys x 64 dims) ----
    auto issue_tile = [&](int t) {
        const int key0 = t << 6;
        const uint32_t kbb = (t & 1) ? kb1 : kb0;
        const uint32_t vbb = (t & 1) ? vb1 : vb0;
        #pragma unroll
        for (int j = 0; j < 8; j++) {
            const int idx = j * 128 + tid;      // 1024 chunks of 16B per tensor
            const int row = idx >> 4;
            const int ch  = (idx & 15) << 2;
            const float* ks = Kg + (size_t)(key0 + row) * RS + ch;
            const float* vs = Vg + (size_t)(key0 + row) * RS + ch;
            asm volatile("cp.async.cg.shared.global [%0], [%1], 16;"
                         :: "r"(kbb + (uint32_t)(row * 68 + ch) * 4), "l"(ks) : "memory");
            asm volatile("cp.async.cg.shared.global [%0], [%1], 16;"
                         :: "r"(vbb + (uint32_t)(row * 72 + ch) * 4), "l"(vs) : "memory");
        }
        asm volatile("cp.async.commit_group;" ::: "memory");
    };

    issue_tile(0);

    // ---- stage Q (f32) into Phi region ----
    #pragma unroll
    for (int i = 0; i < 8; i++) {
        const int idx = i * 128 + tid;          // 1024 float4s
        const int row = idx >> 4;
        const int c4  = (idx & 15) << 2;
        float4 v = *(const float4*)(Qg + (size_t)(q0 + row) * RS + c4);
        float* d = Qs + row * 65 + c4;
        d[0] = v.x; d[1] = v.y; d[2] = v.z; d[3] = v.w;
    }
    __syncthreads();

    // ---- Q frags (rounded tf32) into registers ----
    const int R0 = wid << 4;
    uint32_t qhi[8][4];
    #pragma unroll
    for (int kt = 0; kt < 8; kt++) {
        const int k0 = kt * 8 + tig;
        qhi[kt][0] = f2tf32(Qs[(R0 + r) * 65 + k0]);
        qhi[kt][1] = f2tf32(Qs[(R0 + r + 8) * 65 + k0]);
        qhi[kt][2] = f2tf32(Qs[(R0 + r) * 65 + k0 + 4]);
        qhi[kt][3] = f2tf32(Qs[(R0 + r + 8) * 65 + k0 + 4]);
    }

    float oacc[8][4];
    #pragma unroll
    for (int nt = 0; nt < 8; nt++)
        #pragma unroll
        for (int c = 0; c < 4; c++) oacc[nt][c] = 0.0f;
    float m0 = -1e30f, m1 = -1e30f, l0 = 0.0f, l1 = 0.0f;

    const int rl = R0 + r;
    const int rh = rl + 8;

    #pragma unroll 1
    for (int t = 0; t < NSEQ / 64; t++) {
        asm volatile("cp.async.wait_group 0;" ::: "memory");
        __syncthreads();            // tile t visible; buf (t+1)&1 free

        if (t + 1 < NSEQ / 64) issue_tile(t + 1);

        const uint32_t* Khi = sb + ((t & 1) ? K1_OFF : K0_OFF);
        const uint32_t* Vhi = sb + ((t & 1) ? V1_OFF : V0_OFF);

        // ---- S = Q @ K^T (1-pass, K raw) ----
        float sacc[8][4];
        #pragma unroll
        for (int nt = 0; nt < 8; nt++)
            #pragma unroll
            for (int c = 0; c < 4; c++) sacc[nt][c] = 0.0f;

        #pragma unroll
        for (int kt = 0; kt < 8; kt++) {
            const int k0 = kt * 8 + tig;
            #pragma unroll
            for (int nt = 0; nt < 8; nt++) {
                const int n0 = (nt * 8 + r) * 68;
                MMA_TF32(sacc[nt], qhi[kt], Khi[n0 + k0], Khi[n0 + k0 + 4]);
            }
        }

        // ---- online softmax ----
        float mx0 = -1e30f, mx1 = -1e30f;
        #pragma unroll
        for (int nt = 0; nt < 8; nt++) {
            mx0 = fmaxf(mx0, fmaxf(sacc[nt][0], sacc[nt][1]));
            mx1 = fmaxf(mx1, fmaxf(sacc[nt][2], sacc[nt][3]));
        }
        mx0 = fmaxf(mx0, __shfl_xor_sync(0xffffffffu, mx0, 1));
        mx0 = fmaxf(mx0, __shfl_xor_sync(0xffffffffu, mx0, 2));
        mx1 = fmaxf(mx1, __shfl_xor_sync(0xffffffffu, mx1, 1));
        mx1 = fmaxf(mx1, __shfl_xor_sync(0xffffffffu, mx1, 2));
        const float nm0 = fmaxf(m0, mx0), nm1 = fmaxf(m1, mx1);
        const float cr0 = __expf(m0 - nm0), cr1 = __expf(m1 - nm1);
        float sum0 = 0.0f, sum1 = 0.0f;
        #pragma unroll
        for (int nt = 0; nt < 8; nt++) {
            sacc[nt][0] = __expf(sacc[nt][0] - nm0);
            sacc[nt][1] = __expf(sacc[nt][1] - nm0);
            sacc[nt][2] = __expf(sacc[nt][2] - nm1);
            sacc[nt][3] = __expf(sacc[nt][3] - nm1);
            sum0 += sacc[nt][0] + sacc[nt][1];
            sum1 += sacc[nt][2] + sacc[nt][3];
        }
        sum0 += __shfl_xor_sync(0xffffffffu, sum0, 1);
        sum0 += __shfl_xor_sync(0xffffffffu, sum0, 2);
        sum1 += __shfl_xor_sync(0xffffffffu, sum1, 1);
        sum1 += __shfl_xor_sync(0xffffffffu, sum1, 2);
        l0 = l0 * cr0 + sum0; m0 = nm0;
        l1 = l1 * cr1 + sum1; m1 = nm1;
        #pragma unroll
        for (int nt = 0; nt < 8; nt++) {
            oacc[nt][0] *= cr0; oacc[nt][1] *= cr0;
            oacc[nt][2] *= cr1; oacc[nt][3] *= cr1;
        }

        // ---- P -> tf32 -> smem (warp-local rows) ----
        #pragma unroll
        for (int nt = 0; nt < 8; nt++) {
            const int c = nt * 8 + tig * 2;
            uint64_t p0 = (uint64_t)f2tf32(sacc[nt][0])
                        | ((uint64_t)f2tf32(sacc[nt][1]) << 32);
            uint64_t p1 = (uint64_t)f2tf32(sacc[nt][2])
                        | ((uint64_t)f2tf32(sacc[nt][3]) << 32);
            *(uint64_t*)(Phi + rl * 68 + c) = p0;
            *(uint64_t*)(Phi + rh * 68 + c) = p1;
        }
        __syncwarp();

        // ---- O += P @ V (V raw) ----
        #pragma unroll
        for (int kt = 0; kt < 8; kt++) {
            const int k0 = kt * 8 + tig;
            uint32_t a[4];
            a[0] = Phi[rl * 68 + k0];
            a[1] = Phi[rh * 68 + k0];
            a[2] = Phi[rl * 68 + k0 + 4];
            a[3] = Phi[rh * 68 + k0 + 4];
            #pragma unroll
            for (int nt = 0; nt < 8; nt++) {
                const int n0 = nt * 8 + r;
                MMA_TF32(oacc[nt], a, Vhi[k0 * 72 + n0], Vhi[(k0 + 4) * 72 + n0]);
            }
        }
    }

    // ---- epilogue (1.000338 compensates mean V-truncation shrinkage) ----
    const float inv0 = 1.000338f / l0, inv1 = 1.000338f / l1;
    float* o0 = out + (size_t)(b * NSEQ + q0 + rl) * CDIM + h * HDIM;
    float* o1 = out + (size_t)(b * NSEQ + q0 + rh) * CDIM + h * HDIM;
    #pragma unroll
    for (int nt = 0; nt < 8; nt++) {
        const int c = nt * 8 + tig * 2;
        float2 v0, v1;
        v0.x = oacc[nt][0] * inv0; v0.y = oacc[nt][1] * inv0;
        v1.x = oacc[nt][2] * inv1; v1.y = oacc[nt][3] * inv1;
        *(float2*)(o0 + c) = v0;
        *(float2*)(o1 + c) = v1;
    }
}

extern "C" void kernel_launch(void* const* d_in, const int* in_sizes, int n_in,
                              void* d_out, int out_size)
{
    const float* x    = (const float*)d_in[0];
    const float* w    = (const float*)d_in[1];
    const float* bias = (const float*)d_in[2];
    float* out = (float*)d_out;

    cudaFuncSetAttribute(qkv_gemm_tc,
                         cudaFuncAttributeMaxDynamicSharedMemorySize, GEMM_DSMEM);
    cudaFuncSetAttribute(attn_tc,
                         cudaFuncAttributeMaxDynamicSharedMemorySize, ATTN_DSMEM);

    qkv_gemm_tc<<<dim3(24, 64), 256, GEMM_DSMEM>>>(x, w, bias);
    // 32 q-tiles of 64 rows, B*H = 64
    attn_tc<<<dim3(32, 64), 128, ATTN_DSMEM>>>(out);
}

// round 8
// speedup vs baseline: 2.6116x; 1.0008x over previous
#include <cuda_runtime.h>
#include <math.h>
#include <stdint.h>

#define CDIM 1024
#define NSEQ 2048
#define NHEAD 16
#define HDIM 64
#define RS 3072
#define QK_SCALE 0.125f

__device__ float g_qkv[25165824];   // [8192][3072] qkv scratch

__device__ __forceinline__ uint32_t smem_u32(const void* p) {
    return (uint32_t)__cvta_generic_to_shared(p);
}
__device__ __forceinline__ uint32_t f2tf32(float f) {
    uint32_t r;
    asm("cvt.rna.tf32.f32 %0, %1;" : "=r"(r) : "f"(f));
    return r;
}

#define MMA_TF32(d, a, b0, b1) \
    asm volatile( \
        "mma.sync.aligned.m16n8k8.row.col.f32.tf32.tf32.f32 " \
        "{%0,%1,%2,%3}, {%4,%5,%6,%7}, {%8,%9}, {%0,%1,%2,%3};" \
        : "+f"((d)[0]), "+f"((d)[1]), "+f"((d)[2]), "+f"((d)[3]) \
        : "r"((a)[0]), "r"((a)[1]), "r"((a)[2]), "r"((a)[3]), \
          "r"(b0), "r"(b1))

// ============================================================================
// Kernel 1: mma.sync tf32 GEMM, 2-pass split (unchanged, proven).
// ============================================================================
#define SROW 36
#define STAGE_F (2 * 128 * SROW)
#define GEMM_DSMEM (3 * STAGE_F * 4)

__global__ __launch_bounds__(256, 1) void qkv_gemm_tc(
    const float* __restrict__ X, const float* __restrict__ W,
    const float* __restrict__ bias)
{
    extern __shared__ float smg[];
    const int t    = threadIdx.x;
    const int wid  = t >> 5;
    const int lane = t & 31;
    const int gid  = lane >> 2;
    const int tig  = lane & 3;
    const int wm   = wid >> 2;
    const int wn   = wid & 3;
    const int bm   = blockIdx.y * 128;
    const int bn   = blockIdx.x * 128;

    float acc[4][4][4];
    #pragma unroll
    for (int mi = 0; mi < 4; mi++)
        #pragma unroll
        for (int ni = 0; ni < 4; ni++)
            #pragma unroll
            for (int r = 0; r < 4; r++) acc[mi][ni][r] = 0.0f;

    const int lrow = t >> 3;
    const int lc4  = t & 7;

    auto load_stage = [&](int s) {
        float* A  = smg + (s % 3) * STAGE_F;
        const uint32_t ab = smem_u32(A);
        const uint32_t bb = ab + 128 * SROW * 4;
        #pragma unroll
        for (int i = 0; i < 4; i++) {
            const int row = i * 32 + lrow;
            const uint32_t so = (uint32_t)(row * (SROW * 4) + lc4 * 16);
            const float* sa = X + (size_t)(bm + row) * CDIM + s * 32 + lc4 * 4;
            const float* sw = W + (size_t)(bn + row) * CDIM + s * 32 + lc4 * 4;
            asm volatile("cp.async.cg.shared.global [%0], [%1], 16;"
                         :: "r"(ab + so), "l"(sa) : "memory");
            asm volatile("cp.async.cg.shared.global [%0], [%1], 16;"
                         :: "r"(bb + so), "l"(sw) : "memory");
        }
        asm volatile("cp.async.commit_group;" ::: "memory");
    };

    load_stage(0);
    load_stage(1);

    for (int kt = 0; kt < CDIM / 32; kt++) {
        asm volatile("cp.async.wait_group 1;" ::: "memory");
        __syncthreads();

        if (kt + 2 < CDIM / 32) load_stage(kt + 2);
        else asm volatile("cp.async.commit_group;" ::: "memory");

        const float* A  = smg + (kt % 3) * STAGE_F;
        const float* Bs = A + 128 * SROW;

        #pragma unroll
        for (int ks = 0; ks < 4; ks++) {
            const int k0 = ks * 8 + tig;
            uint32_t ahi[4][4], alo[4][4], bhi[4][2];
            #pragma unroll
            for (int mi = 0; mi < 4; mi++) {
                const int r0 = (wm * 64 + mi * 16 + gid) * SROW;
                float a0 = A[r0 + k0];
                float a1 = A[r0 + 8 * SROW + k0];
                float a2 = A[r0 + k0 + 4];
                float a3 = A[r0 + 8 * SROW + k0 + 4];
                ahi[mi][0] = f2tf32(a0); alo[mi][0] = f2tf32(a0 - __uint_as_float(ahi[mi][0]));
                ahi[mi][1] = f2tf32(a1); alo[mi][1] = f2tf32(a1 - __uint_as_float(ahi[mi][1]));
                ahi[mi][2] = f2tf32(a2); alo[mi][2] = f2tf32(a2 - __uint_as_float(ahi[mi][2]));
                ahi[mi][3] = f2tf32(a3); alo[mi][3] = f2tf32(a3 - __uint_as_float(ahi[mi][3]));
            }
            #pragma unroll
            for (int ni = 0; ni < 4; ni++) {
                const int n0 = (wn * 32 + ni * 8 + gid) * SROW;
                bhi[ni][0] = f2tf32(Bs[n0 + k0]);
                bhi[ni][1] = f2tf32(Bs[n0 + k0 + 4]);
            }
            #pragma unroll
            for (int mi = 0; mi < 4; mi++)
                #pragma unroll
                for (int ni = 0; ni < 4; ni++) {
                    MMA_TF32(acc[mi][ni], ahi[mi], bhi[ni][0], bhi[ni][1]);
                    MMA_TF32(acc[mi][ni], alo[mi], bhi[ni][0], bhi[ni][1]);
                }
        }
        __syncthreads();
    }

    const float cs = (bn < CDIM) ? QK_SCALE : 1.0f;
    #pragma unroll
    for (int mi = 0; mi < 4; mi++) {
        const int r0 = bm + wm * 64 + mi * 16 + gid;
        #pragma unroll
        for (int ni = 0; ni < 4; ni++) {
            const int c = bn + wn * 32 + ni * 8 + tig * 2;
            const float b0 = bias[c], b1 = bias[c + 1];
            float2 v0, v1;
            v0.x = (acc[mi][ni][0] + b0) * cs;
            v0.y = (acc[mi][ni][1] + b1) * cs;
            v1.x = (acc[mi][ni][2] + b0) * cs;
            v1.y = (acc[mi][ni][3] + b1) * cs;
            *(float2*)(g_qkv + (size_t)r0 * RS + c)       = v0;
            *(float2*)(g_qkv + (size_t)(r0 + 8) * RS + c) = v1;
        }
    }
}

// ============================================================================
// Kernel 2: tensor-core flash attention, v3.
// 128 threads (4 warps), 64 q-rows per CTA, 89KB smem -> 2 CTAs/SM so the
// two co-resident CTAs' softmax/MMA phases interleave (independent barriers).
// QK: 1-pass, Q rounded tf32 (regs), K raw f32 (truncated by MMA).
// PV: 1-pass, P rounded tf32, V raw. Epilogue corrects V-truncation bias.
// smem u32: K[2][64][68], V[2][64][72], Phi [64][68] (Q staged in Phi).
// ============================================================================
#define K0_OFF 0
#define K1_OFF 4352
#define V0_OFF 8704
#define V1_OFF 13312
#define PHI_OFF 17920
#define ATTN_DSMEM (22272 * 4)   // 89088 bytes

__global__ __launch_bounds__(128, 2) void attn_tc(float* __restrict__ out)
{
    extern __shared__ uint32_t sb[];
    uint32_t* Phi = sb + PHI_OFF;
    float*    Qs  = (float*)Phi;              // staging view [64][65]

    const int tid  = threadIdx.x;
    const int wid  = tid >> 5;
    const int lane = tid & 31;
    const int r    = lane >> 2;
    const int tig  = lane & 3;
    const int bh   = blockIdx.y;
    const int b    = bh >> 4;
    const int h    = bh & 15;
    const int q0   = blockIdx.x << 6;

    const float* Qg = g_qkv + (size_t)(b * NSEQ) * RS + h * HDIM;
    const float* Kg = Qg + CDIM;
    const float* Vg = Qg + 2 * CDIM;

    const uint32_t sbase = smem_u32(sb);
    const uint32_t kb0 = sbase + K0_OFF * 4, kb1 = sbase + K1_OFF * 4;
    const uint32_t vb0 = sbase + V0_OFF * 4, vb1 = sbase + V1_OFF * 4;

    // ---- double-buffered raw K/V tile copy (64 keys x 64 dims) ----
    auto issue_tile = [&](int t) {
        const int key0 = t << 6;
        const uint32_t kbb = (t & 1) ? kb1 : kb0;
        const uint32_t vbb = (t & 1) ? vb1 : vb0;
        #pragma unroll
        for (int j = 0; j < 8; j++) {
            const int idx = j * 128 + tid;      // 1024 chunks of 16B per tensor
            const int row = idx >> 4;
            const int ch  = (idx & 15) << 2;
            const float* ks = Kg + (size_t)(key0 + row) * RS + ch;
            const float* vs = Vg + (size_t)(key0 + row) * RS + ch;
            asm volatile("cp.async.cg.shared.global [%0], [%1], 16;"
                         :: "r"(kbb + (uint32_t)(row * 68 + ch) * 4), "l"(ks) : "memory");
            asm volatile("cp.async.cg.shared.global [%0], [%1], 16;"
                         :: "r"(vbb + (uint32_t)(row * 72 + ch) * 4), "l"(vs) : "memory");
        }
        asm volatile("cp.async.commit_group;" ::: "memory");
    };

    issue_tile(0);

    // ---- stage Q (f32) into Phi region ----
    #pragma unroll
    for (int i = 0; i < 8; i++) {
        const int idx = i * 128 + tid;          // 1024 float4s
        const int row = idx >> 4;
        const int c4  = (idx & 15) << 2;
        float4 v = *(const float4*)(Qg + (size_t)(q0 + row) * RS + c4);
        float* d = Qs + row * 65 + c4;
        d[0] = v.x; d[1] = v.y; d[2] = v.z; d[3] = v.w;
    }
    __syncthreads();

    // ---- Q frags (rounded tf32) into registers ----
    const int R0 = wid << 4;
    uint32_t qhi[8][4];
    #pragma unroll
    for (int kt = 0; kt < 8; kt++) {
        const int k0 = kt * 8 + tig;
        qhi[kt][0] = f2tf32(Qs[(R0 + r) * 65 + k0]);
        qhi[kt][1] = f2tf32(Qs[(R0 + r + 8) * 65 + k0]);
        qhi[kt][2] = f2tf32(Qs[(R0 + r) * 65 + k0 + 4]);
        qhi[kt][3] = f2tf32(Qs[(R0 + r + 8) * 65 + k0 + 4]);
    }

    float oacc[8][4];
    #pragma unroll
    for (int nt = 0; nt < 8; nt++)
        #pragma unroll
        for (int c = 0; c < 4; c++) oacc[nt][c] = 0.0f;
    float m0 = -1e30f, m1 = -1e30f, l0 = 0.0f, l1 = 0.0f;

    const int rl = R0 + r;
    const int rh = rl + 8;

    #pragma unroll 1
    for (int t = 0; t < NSEQ / 64; t++) {
        asm volatile("cp.async.wait_group 0;" ::: "memory");
        __syncthreads();            // tile t visible; buf (t+1)&1 free

        if (t + 1 < NSEQ / 64) issue_tile(t + 1);

        const uint32_t* Khi = sb + ((t & 1) ? K1_OFF : K0_OFF);
        const uint32_t* Vhi = sb + ((t & 1) ? V1_OFF : V0_OFF);

        // ---- S = Q @ K^T (1-pass, K raw) ----
        float sacc[8][4];
        #pragma unroll
        for (int nt = 0; nt < 8; nt++)
            #pragma unroll
            for (int c = 0; c < 4; c++) sacc[nt][c] = 0.0f;

        #pragma unroll
        for (int kt = 0; kt < 8; kt++) {
            const int k0 = kt * 8 + tig;
            #pragma unroll
            for (int nt = 0; nt < 8; nt++) {
                const int n0 = (nt * 8 + r) * 68;
                MMA_TF32(sacc[nt], qhi[kt], Khi[n0 + k0], Khi[n0 + k0 + 4]);
            }
        }

        // ---- online softmax ----
        float mx0 = -1e30f, mx1 = -1e30f;
        #pragma unroll
        for (int nt = 0; nt < 8; nt++) {
            mx0 = fmaxf(mx0, fmaxf(sacc[nt][0], sacc[nt][1]));
            mx1 = fmaxf(mx1, fmaxf(sacc[nt][2], sacc[nt][3]));
        }
        mx0 = fmaxf(mx0, __shfl_xor_sync(0xffffffffu, mx0, 1));
        mx0 = fmaxf(mx0, __shfl_xor_sync(0xffffffffu, mx0, 2));
        mx1 = fmaxf(mx1, __shfl_xor_sync(0xffffffffu, mx1, 1));
        mx1 = fmaxf(mx1, __shfl_xor_sync(0xffffffffu, mx1, 2));
        const float nm0 = fmaxf(m0, mx0), nm1 = fmaxf(m1, mx1);
        const float cr0 = __expf(m0 - nm0), cr1 = __expf(m1 - nm1);
        float sum0 = 0.0f, sum1 = 0.0f;
        #pragma unroll
        for (int nt = 0; nt < 8; nt++) {
            sacc[nt][0] = __expf(sacc[nt][0] - nm0);
            sacc[nt][1] = __expf(sacc[nt][1] - nm0);
            sacc[nt][2] = __expf(sacc[nt][2] - nm1);
            sacc[nt][3] = __expf(sacc[nt][3] - nm1);
            sum0 += sacc[nt][0] + sacc[nt][1];
            sum1 += sacc[nt][2] + sacc[nt][3];
        }
        sum0 += __shfl_xor_sync(0xffffffffu, sum0, 1);
        sum0 += __shfl_xor_sync(0xffffffffu, sum0, 2);
        sum1 += __shfl_xor_sync(0xffffffffu, sum1, 1);
        sum1 += __shfl_xor_sync(0xffffffffu, sum1, 2);
        l0 = l0 * cr0 + sum0; m0 = nm0;
        l1 = l1 * cr1 + sum1; m1 = nm1;
        #pragma unroll
        for (int nt = 0; nt < 8; nt++) {
            oacc[nt][0] *= cr0; oacc[nt][1] *= cr0;
            oacc[nt][2] *= cr1; oacc[nt][3] *= cr1;
        }

        // ---- P -> tf32 -> smem (warp-local rows) ----
        #pragma unroll
        for (int nt = 0; nt < 8; nt++) {
            const int c = nt * 8 + tig * 2;
            uint64_t p0 = (uint64_t)f2tf32(sacc[nt][0])
                        | ((uint64_t)f2tf32(sacc[nt][1]) << 32);
            uint64_t p1 = (uint64_t)f2tf32(sacc[nt][2])
                        | ((uint64_t)f2tf32(sacc[nt][3]) << 32);
            *(uint64_t*)(Phi + rl * 68 + c) = p0;
            *(uint64_t*)(Phi + rh * 68 + c) = p1;
        }
        __syncwarp();

        // ---- O += P @ V (V raw) ----
        #pragma unroll
        for (int kt = 0; kt < 8; kt++) {
            const int k0 = kt * 8 + tig;
            uint32_t a[4];
            a[0] = Phi[rl * 68 + k0];
            a[1] = Phi[rh * 68 + k0];
            a[2] = Phi[rl * 68 + k0 + 4];
            a[3] = Phi[rh * 68 + k0 + 4];
            #pragma unroll
            for (int nt = 0; nt < 8; nt++) {
                const int n0 = nt * 8 + r;
                MMA_TF32(oacc[nt], a, Vhi[k0 * 72 + n0], Vhi[(k0 + 4) * 72 + n0]);
            }
        }
    }

    // ---- epilogue (1.000338 compensates mean V-truncation shrinkage) ----
    const float inv0 = 1.000338f / l0, inv1 = 1.000338f / l1;
    float* o0 = out + (size_t)(b * NSEQ + q0 + rl) * CDIM + h * HDIM;
    float* o1 = out + (size_t)(b * NSEQ + q0 + rh) * CDIM + h * HDIM;
    #pragma unroll
    for (int nt = 0; nt < 8; nt++) {
        const int c = nt * 8 + tig * 2;
        float2 v0, v1;
        v0.x = oacc[nt][0] * inv0; v0.y = oacc[nt][1] * inv0;
        v1.x = oacc[nt][2] * inv1; v1.y = oacc[nt][3] * inv1;
        *(float2*)(o0 + c) = v0;
        *(float2*)(o1 + c) = v1;
    }
}

extern "C" void kernel_launch(void* const* d_in, const int* in_sizes, int n_in,
                              void* d_out, int out_size)
{
    const float* x    = (const float*)d_in[0];
    const float* w    = (const float*)d_in[1];
    const float* bias = (const float*)d_in[2];
    float* out = (float*)d_out;

    cudaFuncSetAttribute(qkv_gemm_tc,
                         cudaFuncAttributeMaxDynamicSharedMemorySize, GEMM_DSMEM);
    cudaFuncSetAttribute(attn_tc,
                         cudaFuncAttributeMaxDynamicSharedMemorySize, ATTN_DSMEM);

    qkv_gemm_tc<<<dim3(24, 64), 256, GEMM_DSMEM>>>(x, w, bias);
    // 32 q-tiles of 64 rows, B*H = 64
    attn_tc<<<dim3(32, 64), 128, ATTN_DSMEM>>>(out);
}